// round 6
// baseline (speedup 1.0000x reference)
#include <cuda_runtime.h>
#include <cstdint>

#define B_  16
#define S_  64
#define T_  64
#define E_  256
#define H_  512
#define VS_ 32000
#define MM_ 100
#define J_  201
#define BT_ (B_*T_)
#define G4_ (4*H_)

__device__ float d_x[BT_*E_];
__device__ float d_xrev[BT_*E_];
__device__ float d_gpre_fw[BT_*G4_];
__device__ float d_gpre_bw[BT_*G4_];
__device__ float d_gpart[4*2*B_*G4_];
__device__ float d_hstate[2*B_*H_];
__device__ float d_cstate[2*B_*H_];
__device__ float d_hcat[BT_*2*H_];
__device__ float d_ts[BT_*H_];
__device__ float d_logits[(size_t)BT_*VS_];
__device__ float d_rowmax[BT_];
__device__ float d_rowsum[BT_];
__device__ float d_nullstate[H_];
__device__ float d_nulllog[VS_];
__device__ float d_nullred[2];
__device__ float d_tmpt[BT_*E_];
__device__ float d_tt[BT_*H_];
__device__ float d_jl[BT_*J_];
__device__ float d_p0v[BT_];

__device__ __forceinline__ float sigmf(float x){ return 1.f/(1.f+expf(-x)); }

__global__ void k_init(){
    int i = blockIdx.x*blockDim.x + threadIdx.x;
    if (i < 2*B_*H_){ d_hstate[i]=0.f; d_cstate[i]=0.f; }
}

__global__ void k_embed(const int* __restrict__ targets, const int* __restrict__ lengths,
                        const float* __restrict__ emb){
    int bt = blockIdx.x, b = bt/T_, t = bt%T_;
    int len = lengths[b];
    int rt = (t < len) ? (len-1-t) : t;
    int r0 = targets[bt], r1 = targets[b*T_+rt];
    for (int e = threadIdx.x; e < E_; e += blockDim.x){
        d_x[bt*E_+e]    = emb[(size_t)r0*E_+e];
        d_xrev[bt*E_+e] = emb[(size_t)r1*E_+e];
    }
}

__global__ void k_nullstate(const int* __restrict__ tnull, const float* __restrict__ emb,
                            const float* __restrict__ nnW, const float* __restrict__ nnb){
    __shared__ float xe[E_];
    int tid = threadIdx.x;          // 512
    int r = tnull[0];
    for (int e = tid; e < E_; e += blockDim.x) xe[e] = emb[(size_t)r*E_+e];
    __syncthreads();
    float a = nnb[tid];
    #pragma unroll 4
    for (int e = 0; e < E_; e++) a = fmaf(xe[e], nnW[e*H_+tid], a);
    d_nullstate[tid] = tanhf(a);
}

// tiled SGEMM, packed f32x2 FMA. C = A[MxK] @ B[KxN] (+bias) (+tanh if ACT)
template<int ACT>
__global__ void sgemm_k(const float* __restrict__ A, const float* __restrict__ Bm,
                        const float* __restrict__ bias, float* __restrict__ C,
                        int M, int N, int K)
{
    const int BM=64, BN=128, BK=16, TM=4, TN=8, THREADS=256;
    __shared__ float As[BM][BK+1];
    __shared__ __align__(16) float Bs[BK][BN];
    int tid = threadIdx.x;
    int tx = tid % (BN/TN), ty = tid / (BN/TN);
    int row0 = blockIdx.y*BM, col0 = blockIdx.x*BN;
    unsigned long long acc2[TM][TN/2];
    #pragma unroll
    for (int m=0;m<TM;m++){
        #pragma unroll
        for (int i=0;i<TN/2;i++) acc2[m][i]=0ull;
    }
    for (int k0 = 0; k0 < K; k0 += BK){
        for (int l = tid; l < BM*BK; l += THREADS){
            int r=l/BK, c=l%BK;
            As[r][c] = A[(size_t)(row0+r)*K + k0 + c];
        }
        for (int l = tid; l < BK*BN; l += THREADS){
            int r=l/BN, c=l%BN, gc=col0+c;
            Bs[r][c] = (gc<N) ? Bm[(size_t)(k0+r)*N + gc] : 0.f;
        }
        __syncthreads();
        #pragma unroll
        for (int kk=0; kk<BK; kk++){
            unsigned long long b2[TN/2];
            #pragma unroll
            for (int i=0;i<TN/2;i++)
                b2[i] = *reinterpret_cast<const unsigned long long*>(&Bs[kk][tx*TN+2*i]);
            #pragma unroll
            for (int m=0;m<TM;m++){
                float av = As[ty*TM+m][kk];
                unsigned long long a2;
                asm("mov.b64 %0, {%1, %1};" : "=l"(a2) : "r"(__float_as_uint(av)));
                #pragma unroll
                for (int i=0;i<TN/2;i++)
                    asm("fma.rn.f32x2 %0, %1, %2, %0;" : "+l"(acc2[m][i]) : "l"(a2), "l"(b2[i]));
            }
        }
        __syncthreads();
    }
    #pragma unroll
    for (int m=0;m<TM;m++){
        int gr = row0 + ty*TM + m;
        #pragma unroll
        for (int i=0;i<TN/2;i++){
            unsigned lo,hi;
            asm("mov.b64 {%0, %1}, %2;" : "=r"(lo), "=r"(hi) : "l"(acc2[m][i]));
            int gc0 = col0 + tx*TN + 2*i;
            if (gc0 < N){
                float v = __uint_as_float(lo);
                if (bias) v += bias[gc0];
                if (ACT) v = tanhf(v);
                C[(size_t)gr*N + gc0] = v;
            }
            if (gc0+1 < N){
                float v = __uint_as_float(hi);
                if (bias) v += bias[gc0+1];
                if (ACT) v = tanhf(v);
                C[(size_t)gr*N + gc0+1] = v;
            }
        }
    }
}

// recurrent GEMM: gpart[ks,dir,b,4H] = h_prev[dir,b,:]@Wh[dir] (split-K x4)
__global__ void k_lstm_gemm(const float* __restrict__ Wh_fw, const float* __restrict__ Wh_bw){
    int chunk = blockIdx.x, dir = blockIdx.y, ks = blockIdx.z;
    int tid = threadIdx.x;
    int colid = tid & 127, bg = tid >> 7;
    __shared__ __align__(16) float hsT[128*16];   // [k][b]
    const float* hprev = d_hstate + dir*(B_*H_);
    for (int i = tid; i < 128*16; i += 256){
        int k = i>>4, b = i&15;
        hsT[i] = hprev[b*H_ + ks*128 + k];
    }
    __syncthreads();
    const float* Wh = dir ? Wh_bw : Wh_fw;
    int colg = chunk*128 + colid;
    const float* wp = Wh + (size_t)(ks*128)*G4_ + colg;
    unsigned long long acc2[4] = {0,0,0,0};
    #pragma unroll 4
    for (int k = 0; k < 128; k++){
        float w = wp[(size_t)k*G4_];
        unsigned long long w2;
        asm("mov.b64 %0, {%1, %1};" : "=l"(w2) : "r"(__float_as_uint(w)));
        const unsigned long long* hv = reinterpret_cast<const unsigned long long*>(&hsT[k*16 + bg*8]);
        #pragma unroll
        for (int j=0;j<4;j++)
            asm("fma.rn.f32x2 %0, %1, %2, %0;" : "+l"(acc2[j]) : "l"(hv[j]), "l"(w2));
    }
    float* gp = d_gpart + ((size_t)(ks*2+dir)*B_ + bg*8)*G4_ + colg;
    #pragma unroll
    for (int j=0;j<4;j++){
        unsigned lo,hi;
        asm("mov.b64 {%0, %1}, %2;" : "=r"(lo), "=r"(hi) : "l"(acc2[j]));
        gp[(size_t)(2*j)*G4_]   = __uint_as_float(lo);
        gp[(size_t)(2*j+1)*G4_] = __uint_as_float(hi);
    }
}

__global__ void k_lstm_combine(const int* __restrict__ lengths, int t){
    int b = blockIdx.x, dir = blockIdx.y, h = threadIdx.x;   // 512
    const float* gp = (dir ? d_gpre_bw : d_gpre_fw) + (size_t)(b*T_+t)*G4_;
    float g[4];
    #pragma unroll
    for (int gt=0; gt<4; gt++){
        float a = gp[gt*H_+h];
        #pragma unroll
        for (int ks=0; ks<4; ks++)
            a += d_gpart[((size_t)(ks*2+dir)*B_ + b)*G4_ + gt*H_ + h];
        g[gt] = a;
    }
    int idx = (dir*B_+b)*H_+h;
    float c = d_cstate[idx], hp = d_hstate[idx];
    float cn = sigmf(g[2]+1.f)*c + sigmf(g[0])*tanhf(g[1]);
    float hn = sigmf(g[3])*tanhf(cn);
    int len = lengths[b];
    bool m = (t < len);
    d_cstate[idx] = m ? cn : c;
    d_hstate[idx] = m ? hn : hp;
    float ho = m ? hn : 0.f;
    if (dir == 0) d_hcat[(size_t)(b*T_+t)*(2*H_) + h] = ho;
    else { int p = m ? (len-1-t) : t; d_hcat[(size_t)(b*T_+p)*(2*H_) + H_ + h] = ho; }
}

__global__ void k_rowreduce(){
    int row = blockIdx.x, tid = threadIdx.x;
    const float* p = d_logits + (size_t)row*VS_;
    __shared__ float sm[256];
    float m = -1e30f;
    for (int v=tid; v<VS_; v+=256) m = fmaxf(m, p[v]);
    sm[tid]=m; __syncthreads();
    for (int s=128;s>0;s>>=1){ if(tid<s) sm[tid]=fmaxf(sm[tid],sm[tid+s]); __syncthreads(); }
    float mx = sm[0]; __syncthreads();
    float su = 0.f;
    for (int v=tid; v<VS_; v+=256) su += expf(p[v]-mx);
    sm[tid]=su; __syncthreads();
    for (int s=128;s>0;s>>=1){ if(tid<s) sm[tid]+=sm[tid+s]; __syncthreads(); }
    if (tid==0){ d_rowmax[row]=mx; d_rowsum[row]=sm[0]; }
}

__global__ void k_nulllogits(const float* __restrict__ Wv, const float* __restrict__ bv){
    __shared__ float ns[H_];
    int tid = threadIdx.x;
    for (int k=tid; k<H_; k+=256) ns[k] = d_nullstate[k];
    __syncthreads();
    int v = blockIdx.x*256 + tid;
    if (v < VS_){
        float a = bv[v];
        #pragma unroll 4
        for (int k=0;k<H_;k++) a = fmaf(ns[k], Wv[(size_t)k*VS_+v], a);
        d_nulllog[v] = a;
    }
}

__global__ void k_nullreduce(){
    __shared__ float sm[1024];
    int tid = threadIdx.x;
    float m = -1e30f;
    for (int v=tid; v<VS_; v+=1024) m = fmaxf(m, d_nulllog[v]);
    sm[tid]=m; __syncthreads();
    for (int s=512;s>0;s>>=1){ if(tid<s) sm[tid]=fmaxf(sm[tid],sm[tid+s]); __syncthreads(); }
    float mx = sm[0]; __syncthreads();
    float su = 0.f;
    for (int v=tid; v<VS_; v+=1024) su += expf(d_nulllog[v]-mx);
    sm[tid]=su; __syncthreads();
    for (int s=512;s>0;s>>=1){ if(tid<s) sm[tid]+=sm[tid+s]; __syncthreads(); }
    if (tid==0){ d_nullred[0]=mx; d_nullred[1]=sm[0]; }
}

__global__ void k_emission(const int* __restrict__ sources, float* __restrict__ out){
    int bt = blockIdx.x, b = bt>>6, t = bt&63, s = threadIdx.x;   // 64
    int col = sources[b*S_+s];
    float l = d_logits[(size_t)bt*VS_ + col];
    out[(size_t)b*(2*T_*S_) + t*S_ + s] = expf(l - d_rowmax[bt]) / d_rowsum[bt];
    out[(size_t)b*(2*T_*S_) + (T_+t)*S_ + s] = expf(d_nulllog[col]-d_nullred[0]) / d_nullred[1];
}

__global__ void k_jsoftmax(){
    int row = blockIdx.x, tid = threadIdx.x;
    float* p = d_jl + (size_t)row*J_;
    __shared__ float sm[256];
    float m = -1e30f;
    for (int j=tid; j<J_; j+=256) m = fmaxf(m, p[j]);
    sm[tid]=m; __syncthreads();
    for (int s=128;s>0;s>>=1){ if(tid<s) sm[tid]=fmaxf(sm[tid],sm[tid+s]); __syncthreads(); }
    float mx = sm[0]; __syncthreads();
    float su = 0.f;
    for (int j=tid; j<J_; j+=256) su += expf(p[j]-mx);
    sm[tid]=su; __syncthreads();
    for (int s=128;s>0;s>>=1){ if(tid<s) sm[tid]+=sm[tid+s]; __syncthreads(); }
    float inv = 1.f/sm[0]; __syncthreads();
    for (int j=tid; j<J_; j+=256) p[j] = expf(p[j]-mx)*inv;
}

__global__ void k_p0(const float* __restrict__ Wp0, const float* __restrict__ bp0){
    int gw = (blockIdx.x*blockDim.x + threadIdx.x) >> 5;
    int lane = threadIdx.x & 31;
    if (gw >= BT_) return;
    float a = 0.f;
    for (int k=lane; k<H_; k+=32) a = fmaf(d_tt[(size_t)gw*H_+k], Wp0[k], a);
    #pragma unroll
    for (int o=16;o>0;o>>=1) a += __shfl_xor_sync(0xffffffffu, a, o);
    if (lane==0) d_p0v[gw] = sigmf(a + bp0[0]);
}

__global__ void k_transition(float* __restrict__ out){
    int b = blockIdx.y;
    int idx = blockIdx.x*256 + threadIdx.x;     // over T*2T = 8192
    if (idx >= T_*2*T_) return;
    int i = idx / (2*T_), c = idx % (2*T_);
    float tv, lv;
    if (c < T_){
        float jw = d_jl[(size_t)(b*T_+i)*J_ + (MM_ + c - i)];
        tv = jw; lv = logf(jw);
    } else {
        int j = c - T_;
        float p = d_p0v[b*T_+i];
        tv = (i==j) ? p : 0.f;
        lv = (i==j) ? logf(p) : 0.f;
    }
    float* tr  = out + (size_t)B_*2*T_*S_ + (size_t)b*(2*T_*2*T_);
    float* trl = tr + (size_t)B_*2*T_*2*T_;
    tr [i*2*T_ + c] = tv;  tr [(T_+i)*2*T_ + c] = tv;
    trl[i*2*T_ + c] = lv;  trl[(T_+i)*2*T_ + c] = lv;
}

extern "C" void kernel_launch(void* const* d_in, const int* in_sizes, int n_in,
                              void* d_out, int out_size) {
    const int*   sources = (const int*)  d_in[0];
    const int*   targets = (const int*)  d_in[1];
    const int*   tnull   = (const int*)  d_in[2];
    const int*   lengths = (const int*)  d_in[3];
    const float* emb     = (const float*)d_in[4];
    const float* nnW     = (const float*)d_in[5];
    const float* nnb     = (const float*)d_in[6];
    const float* Wx_fw   = (const float*)d_in[7];
    const float* Wh_fw   = (const float*)d_in[8];
    const float* b_fw    = (const float*)d_in[9];
    const float* Wx_bw   = (const float*)d_in[10];
    const float* Wh_bw   = (const float*)d_in[11];
    const float* b_bw    = (const float*)d_in[12];
    const float* Wproj_e = (const float*)d_in[13];
    const float* Wv      = (const float*)d_in[14];
    const float* bv      = (const float*)d_in[15];
    const float* Wproj_t = (const float*)d_in[16];
    const float* Wj      = (const float*)d_in[17];
    const float* bj      = (const float*)d_in[18];
    const float* Wp0     = (const float*)d_in[19];
    const float* bp0     = (const float*)d_in[20];
    float* out = (float*)d_out;

    float *gfw, *gbw, *xp, *xrp, *hc, *tsp, *lg, *tmp, *ttp, *jl;
    cudaGetSymbolAddress((void**)&gfw, d_gpre_fw);
    cudaGetSymbolAddress((void**)&gbw, d_gpre_bw);
    cudaGetSymbolAddress((void**)&xp,  d_x);
    cudaGetSymbolAddress((void**)&xrp, d_xrev);
    cudaGetSymbolAddress((void**)&hc,  d_hcat);
    cudaGetSymbolAddress((void**)&tsp, d_ts);
    cudaGetSymbolAddress((void**)&lg,  d_logits);
    cudaGetSymbolAddress((void**)&tmp, d_tmpt);
    cudaGetSymbolAddress((void**)&ttp, d_tt);
    cudaGetSymbolAddress((void**)&jl,  d_jl);

    k_init<<<64,256>>>();
    k_embed<<<BT_,256>>>(targets, lengths, emb);
    k_nullstate<<<1,512>>>(tnull, emb, nnW, nnb);

    // input projections for all timesteps
    sgemm_k<0><<<dim3(16,16),256>>>(xp,  Wx_fw, b_fw, gfw, BT_, G4_, E_);
    sgemm_k<0><<<dim3(16,16),256>>>(xrp, Wx_bw, b_bw, gbw, BT_, G4_, E_);

    for (int t = 0; t < T_; t++){
        k_lstm_gemm<<<dim3(16,2,4),256>>>(Wh_fw, Wh_bw);
        k_lstm_combine<<<dim3(B_,2),512>>>(lengths, t);
    }

    // emission path
    sgemm_k<0><<<dim3(4,16),256>>>(hc, Wproj_e, nullptr, tsp, BT_, H_, 2*H_);
    sgemm_k<0><<<dim3(250,16),256>>>(tsp, Wv, bv, lg, BT_, VS_, H_);
    k_rowreduce<<<BT_,256>>>();
    k_nulllogits<<<125,256>>>(Wv, bv);
    k_nullreduce<<<1,1024>>>();
    k_emission<<<BT_,64>>>(sources, out);

    // transition path
    sgemm_k<0><<<dim3(2,16),256>>>(hc, Wproj_t, nullptr, tmp, BT_, E_, 2*H_);
    sgemm_k<1><<<dim3(4,16),256>>>(tmp, nnW, nnb, ttp, BT_, H_, E_);
    sgemm_k<0><<<dim3(2,16),256>>>(ttp, Wj, bj, jl, BT_, J_, H_);
    k_jsoftmax<<<BT_,256>>>();
    k_p0<<<128,256>>>(Wp0, bp0);
    k_transition<<<dim3(32,16),256>>>(out);
}

// round 7
// speedup vs baseline: 1.5485x; 1.5485x over previous
#include <cuda_runtime.h>
#include <cstdint>

#define B_  16
#define S_  64
#define T_  64
#define E_  256
#define H_  512
#define VS_ 32000
#define MM_ 100
#define J_  201
#define BT_ (B_*T_)
#define G4_ (4*H_)

__device__ float d_x[BT_*E_];
__device__ float d_xrev[BT_*E_];
__device__ float d_gpre_fw[BT_*G4_];
__device__ float d_gpre_bw[BT_*G4_];
__device__ float d_gpart[4*2*B_*G4_];
__device__ float d_hstate[2*B_*H_];
__device__ float d_cstate[2*B_*H_];
__device__ float d_hcat[BT_*2*H_];
__device__ float d_ts[BT_*H_];
__device__ float d_logits[(size_t)BT_*VS_];
__device__ float d_rowmax[BT_];
__device__ float d_rowsum[BT_];
__device__ float d_nullstate[H_];
__device__ float d_nulllog[VS_];
__device__ float d_nullred[2];
__device__ float d_tmpt[BT_*E_];
__device__ float d_tt[BT_*H_];
__device__ float d_jl[BT_*J_];
__device__ float d_p0v[BT_];

__device__ __forceinline__ float sigmf(float x){ return 1.f/(1.f+expf(-x)); }
__device__ __forceinline__ uint32_t f2tf32(float v){
    uint32_t r; asm("cvt.rna.tf32.f32 %0, %1;" : "=r"(r) : "f"(v)); return r;
}

__global__ void k_init(){
    int i = blockIdx.x*blockDim.x + threadIdx.x;
    if (i < 2*B_*H_){ d_hstate[i]=0.f; d_cstate[i]=0.f; }
}

__global__ void k_embed(const int* __restrict__ targets, const int* __restrict__ lengths,
                        const float* __restrict__ emb){
    int bt = blockIdx.x, b = bt/T_, t = bt%T_;
    int len = lengths[b];
    int rt = (t < len) ? (len-1-t) : t;
    int r0 = targets[bt], r1 = targets[b*T_+rt];
    for (int e = threadIdx.x; e < E_; e += blockDim.x){
        d_x[bt*E_+e]    = emb[(size_t)r0*E_+e];
        d_xrev[bt*E_+e] = emb[(size_t)r1*E_+e];
    }
}

__global__ void k_nullstate(const int* __restrict__ tnull, const float* __restrict__ emb,
                            const float* __restrict__ nnW, const float* __restrict__ nnb){
    __shared__ float xe[E_];
    int tid = threadIdx.x;          // 512
    int r = tnull[0];
    for (int e = tid; e < E_; e += blockDim.x) xe[e] = emb[(size_t)r*E_+e];
    __syncthreads();
    float a = nnb[tid];
    #pragma unroll 4
    for (int e = 0; e < E_; e++) a = fmaf(xe[e], nnW[e*H_+tid], a);
    d_nullstate[tid] = tanhf(a);
}

// ---------------- tf32 tensor-core GEMM ----------------
// C[M,N] = A[M,K] @ B[K,N] (+bias). Requires M%128==0, N%128==0, K%16==0.
// grid = (M/128, N/128), 256 threads (8 warps: 4 along M, 2 along N).
__global__ void tf32gemm_k(const float* __restrict__ A, const float* __restrict__ Bm,
                           const float* __restrict__ bias, float* __restrict__ C,
                           int M, int N, int K)
{
    __shared__ float As[16][132];   // transposed: As[k][m]
    __shared__ float Bs[16][132];   // Bs[k][n]
    int tid = threadIdx.x, lane = tid & 31, wid = tid >> 5;
    int wm = wid & 3, wn = wid >> 2;
    int gid = lane >> 2, tig = lane & 3;
    int row0 = blockIdx.x * 128, col0 = blockIdx.y * 128;

    float c[2][8][4];
    #pragma unroll
    for (int mt=0; mt<2; mt++)
        #pragma unroll
        for (int nt=0; nt<8; nt++)
            #pragma unroll
            for (int q=0; q<4; q++) c[mt][nt][q] = 0.f;

    for (int k0 = 0; k0 < K; k0 += 16){
        #pragma unroll
        for (int j = 0; j < 2; j++){
            int s = tid*2 + j;               // 512 float4 slots for A (128 rows x 4)
            int r = s >> 2, kq = (s & 3)*4;
            float4 v = *reinterpret_cast<const float4*>(&A[(size_t)(row0 + r)*K + k0 + kq]);
            As[kq+0][r] = __uint_as_float(f2tf32(v.x));
            As[kq+1][r] = __uint_as_float(f2tf32(v.y));
            As[kq+2][r] = __uint_as_float(f2tf32(v.z));
            As[kq+3][r] = __uint_as_float(f2tf32(v.w));
        }
        #pragma unroll
        for (int j = 0; j < 2; j++){
            int s = tid*2 + j;               // 512 float4 slots for B (16 rows x 32)
            int r = s >> 5, c4 = (s & 31)*4;
            float4 v = *reinterpret_cast<const float4*>(&Bm[(size_t)(k0 + r)*N + col0 + c4]);
            Bs[r][c4+0] = __uint_as_float(f2tf32(v.x));
            Bs[r][c4+1] = __uint_as_float(f2tf32(v.y));
            Bs[r][c4+2] = __uint_as_float(f2tf32(v.z));
            Bs[r][c4+3] = __uint_as_float(f2tf32(v.w));
        }
        __syncthreads();
        #pragma unroll
        for (int kk = 0; kk < 2; kk++){
            int kb = kk*8;
            uint32_t a[2][4], b[8][2];
            #pragma unroll
            for (int mt=0; mt<2; mt++){
                int r = wm*32 + mt*16 + gid;
                a[mt][0] = __float_as_uint(As[kb+tig  ][r  ]);
                a[mt][1] = __float_as_uint(As[kb+tig  ][r+8]);
                a[mt][2] = __float_as_uint(As[kb+tig+4][r  ]);
                a[mt][3] = __float_as_uint(As[kb+tig+4][r+8]);
            }
            #pragma unroll
            for (int nt=0; nt<8; nt++){
                int n = wn*64 + nt*8 + gid;
                b[nt][0] = __float_as_uint(Bs[kb+tig  ][n]);
                b[nt][1] = __float_as_uint(Bs[kb+tig+4][n]);
            }
            #pragma unroll
            for (int mt=0; mt<2; mt++)
                #pragma unroll
                for (int nt=0; nt<8; nt++)
                    asm("mma.sync.aligned.m16n8k8.row.col.f32.tf32.tf32.f32 "
                        "{%0,%1,%2,%3}, {%4,%5,%6,%7}, {%8,%9}, {%0,%1,%2,%3};"
                        : "+f"(c[mt][nt][0]), "+f"(c[mt][nt][1]),
                          "+f"(c[mt][nt][2]), "+f"(c[mt][nt][3])
                        : "r"(a[mt][0]), "r"(a[mt][1]), "r"(a[mt][2]), "r"(a[mt][3]),
                          "r"(b[nt][0]), "r"(b[nt][1]));
        }
        __syncthreads();
    }
    #pragma unroll
    for (int mt=0; mt<2; mt++){
        int r = row0 + wm*32 + mt*16 + gid;
        #pragma unroll
        for (int nt=0; nt<8; nt++){
            int cc = col0 + wn*64 + nt*8 + tig*2;
            float b0 = bias ? bias[cc] : 0.f;
            float b1 = bias ? bias[cc+1] : 0.f;
            C[(size_t)r*N + cc]       = c[mt][nt][0] + b0;
            C[(size_t)r*N + cc + 1]   = c[mt][nt][1] + b1;
            C[(size_t)(r+8)*N + cc]   = c[mt][nt][2] + b0;
            C[(size_t)(r+8)*N + cc+1] = c[mt][nt][3] + b1;
        }
    }
}

// tiled SGEMM, packed f32x2 FMA. C = A[MxK] @ B[KxN] (+bias) (+tanh if ACT)
template<int ACT>
__global__ void sgemm_k(const float* __restrict__ A, const float* __restrict__ Bm,
                        const float* __restrict__ bias, float* __restrict__ C,
                        int M, int N, int K)
{
    const int BM=64, BN=128, BK=16, TM=4, TN=8, THREADS=256;
    __shared__ float As[BM][BK+1];
    __shared__ __align__(16) float Bs[BK][BN];
    int tid = threadIdx.x;
    int tx = tid % (BN/TN), ty = tid / (BN/TN);
    int row0 = blockIdx.y*BM, col0 = blockIdx.x*BN;
    unsigned long long acc2[TM][TN/2];
    #pragma unroll
    for (int m=0;m<TM;m++){
        #pragma unroll
        for (int i=0;i<TN/2;i++) acc2[m][i]=0ull;
    }
    for (int k0 = 0; k0 < K; k0 += BK){
        for (int l = tid; l < BM*BK; l += THREADS){
            int r=l/BK, c=l%BK;
            As[r][c] = A[(size_t)(row0+r)*K + k0 + c];
        }
        for (int l = tid; l < BK*BN; l += THREADS){
            int r=l/BN, c=l%BN, gc=col0+c;
            Bs[r][c] = (gc<N) ? Bm[(size_t)(k0+r)*N + gc] : 0.f;
        }
        __syncthreads();
        #pragma unroll
        for (int kk=0; kk<BK; kk++){
            unsigned long long b2[TN/2];
            #pragma unroll
            for (int i=0;i<TN/2;i++)
                b2[i] = *reinterpret_cast<const unsigned long long*>(&Bs[kk][tx*TN+2*i]);
            #pragma unroll
            for (int m=0;m<TM;m++){
                float av = As[ty*TM+m][kk];
                unsigned long long a2;
                asm("mov.b64 %0, {%1, %1};" : "=l"(a2) : "r"(__float_as_uint(av)));
                #pragma unroll
                for (int i=0;i<TN/2;i++)
                    asm("fma.rn.f32x2 %0, %1, %2, %0;" : "+l"(acc2[m][i]) : "l"(a2), "l"(b2[i]));
            }
        }
        __syncthreads();
    }
    #pragma unroll
    for (int m=0;m<TM;m++){
        int gr = row0 + ty*TM + m;
        #pragma unroll
        for (int i=0;i<TN/2;i++){
            unsigned lo,hi;
            asm("mov.b64 {%0, %1}, %2;" : "=r"(lo), "=r"(hi) : "l"(acc2[m][i]));
            int gc0 = col0 + tx*TN + 2*i;
            if (gc0 < N){
                float v = __uint_as_float(lo);
                if (bias) v += bias[gc0];
                if (ACT) v = tanhf(v);
                C[(size_t)gr*N + gc0] = v;
            }
            if (gc0+1 < N){
                float v = __uint_as_float(hi);
                if (bias) v += bias[gc0+1];
                if (ACT) v = tanhf(v);
                C[(size_t)gr*N + gc0+1] = v;
            }
        }
    }
}

// recurrent GEMM: gpart[ks,dir,b,4H] = h_prev[dir,b,:]@Wh[dir] (split-K x4)
__global__ void k_lstm_gemm(const float* __restrict__ Wh_fw, const float* __restrict__ Wh_bw){
    int chunk = blockIdx.x, dir = blockIdx.y, ks = blockIdx.z;
    int tid = threadIdx.x;
    int colid = tid & 127, bg = tid >> 7;
    __shared__ __align__(16) float hsT[128*16];   // [k][b]
    const float* hprev = d_hstate + dir*(B_*H_);
    for (int i = tid; i < 128*16; i += 256){
        int k = i>>4, b = i&15;
        hsT[i] = hprev[b*H_ + ks*128 + k];
    }
    __syncthreads();
    const float* Wh = dir ? Wh_bw : Wh_fw;
    int colg = chunk*128 + colid;
    const float* wp = Wh + (size_t)(ks*128)*G4_ + colg;
    unsigned long long acc2[4] = {0,0,0,0};
    #pragma unroll 4
    for (int k = 0; k < 128; k++){
        float w = wp[(size_t)k*G4_];
        unsigned long long w2;
        asm("mov.b64 %0, {%1, %1};" : "=l"(w2) : "r"(__float_as_uint(w)));
        const unsigned long long* hv = reinterpret_cast<const unsigned long long*>(&hsT[k*16 + bg*8]);
        #pragma unroll
        for (int j=0;j<4;j++)
            asm("fma.rn.f32x2 %0, %1, %2, %0;" : "+l"(acc2[j]) : "l"(hv[j]), "l"(w2));
    }
    float* gp = d_gpart + ((size_t)(ks*2+dir)*B_ + bg*8)*G4_ + colg;
    #pragma unroll
    for (int j=0;j<4;j++){
        unsigned lo,hi;
        asm("mov.b64 {%0, %1}, %2;" : "=r"(lo), "=r"(hi) : "l"(acc2[j]));
        gp[(size_t)(2*j)*G4_]   = __uint_as_float(lo);
        gp[(size_t)(2*j+1)*G4_] = __uint_as_float(hi);
    }
}

__global__ void k_lstm_combine(const int* __restrict__ lengths, int t){
    int b = blockIdx.x, dir = blockIdx.y, h = threadIdx.x;   // 512
    const float* gp = (dir ? d_gpre_bw : d_gpre_fw) + (size_t)(b*T_+t)*G4_;
    float g[4];
    #pragma unroll
    for (int gt=0; gt<4; gt++){
        float a = gp[gt*H_+h];
        #pragma unroll
        for (int ks=0; ks<4; ks++)
            a += d_gpart[((size_t)(ks*2+dir)*B_ + b)*G4_ + gt*H_ + h];
        g[gt] = a;
    }
    int idx = (dir*B_+b)*H_+h;
    float c = d_cstate[idx], hp = d_hstate[idx];
    float cn = sigmf(g[2]+1.f)*c + sigmf(g[0])*tanhf(g[1]);
    float hn = sigmf(g[3])*tanhf(cn);
    int len = lengths[b];
    bool m = (t < len);
    d_cstate[idx] = m ? cn : c;
    d_hstate[idx] = m ? hn : hp;
    float ho = m ? hn : 0.f;
    if (dir == 0) d_hcat[(size_t)(b*T_+t)*(2*H_) + h] = ho;
    else { int p = m ? (len-1-t) : t; d_hcat[(size_t)(b*T_+p)*(2*H_) + H_ + h] = ho; }
}

__global__ void k_rowreduce(){
    int row = blockIdx.x, tid = threadIdx.x;
    const float* p = d_logits + (size_t)row*VS_;
    __shared__ float sm[256];
    float m = -1e30f;
    for (int v=tid; v<VS_; v+=256) m = fmaxf(m, p[v]);
    sm[tid]=m; __syncthreads();
    for (int s=128;s>0;s>>=1){ if(tid<s) sm[tid]=fmaxf(sm[tid],sm[tid+s]); __syncthreads(); }
    float mx = sm[0]; __syncthreads();
    float su = 0.f;
    for (int v=tid; v<VS_; v+=256) su += expf(p[v]-mx);
    sm[tid]=su; __syncthreads();
    for (int s=128;s>0;s>>=1){ if(tid<s) sm[tid]+=sm[tid+s]; __syncthreads(); }
    if (tid==0){ d_rowmax[row]=mx; d_rowsum[row]=sm[0]; }
}

__global__ void k_nulllogits(const float* __restrict__ Wv, const float* __restrict__ bv){
    __shared__ float ns[H_];
    int tid = threadIdx.x;
    for (int k=tid; k<H_; k+=256) ns[k] = d_nullstate[k];
    __syncthreads();
    int v = blockIdx.x*256 + tid;
    if (v < VS_){
        float a = bv[v];
        #pragma unroll 4
        for (int k=0;k<H_;k++) a = fmaf(ns[k], Wv[(size_t)k*VS_+v], a);
        d_nulllog[v] = a;
    }
}

__global__ void k_nullreduce(){
    __shared__ float sm[1024];
    int tid = threadIdx.x;
    float m = -1e30f;
    for (int v=tid; v<VS_; v+=1024) m = fmaxf(m, d_nulllog[v]);
    sm[tid]=m; __syncthreads();
    for (int s=512;s>0;s>>=1){ if(tid<s) sm[tid]=fmaxf(sm[tid],sm[tid+s]); __syncthreads(); }
    float mx = sm[0]; __syncthreads();
    float su = 0.f;
    for (int v=tid; v<VS_; v+=1024) su += expf(d_nulllog[v]-mx);
    sm[tid]=su; __syncthreads();
    for (int s=512;s>0;s>>=1){ if(tid<s) sm[tid]+=sm[tid+s]; __syncthreads(); }
    if (tid==0){ d_nullred[0]=mx; d_nullred[1]=sm[0]; }
}

__global__ void k_emission(const int* __restrict__ sources, float* __restrict__ out){
    int bt = blockIdx.x, b = bt>>6, t = bt&63, s = threadIdx.x;   // 64
    int col = sources[b*S_+s];
    float l = d_logits[(size_t)bt*VS_ + col];
    out[(size_t)b*(2*T_*S_) + t*S_ + s] = expf(l - d_rowmax[bt]) / d_rowsum[bt];
    out[(size_t)b*(2*T_*S_) + (T_+t)*S_ + s] = expf(d_nulllog[col]-d_nullred[0]) / d_nullred[1];
}

__global__ void k_jsoftmax(){
    int row = blockIdx.x, tid = threadIdx.x;
    float* p = d_jl + (size_t)row*J_;
    __shared__ float sm[256];
    float m = -1e30f;
    for (int j=tid; j<J_; j+=256) m = fmaxf(m, p[j]);
    sm[tid]=m; __syncthreads();
    for (int s=128;s>0;s>>=1){ if(tid<s) sm[tid]=fmaxf(sm[tid],sm[tid+s]); __syncthreads(); }
    float mx = sm[0]; __syncthreads();
    float su = 0.f;
    for (int j=tid; j<J_; j+=256) su += expf(p[j]-mx);
    sm[tid]=su; __syncthreads();
    for (int s=128;s>0;s>>=1){ if(tid<s) sm[tid]+=sm[tid+s]; __syncthreads(); }
    float inv = 1.f/sm[0]; __syncthreads();
    for (int j=tid; j<J_; j+=256) p[j] = expf(p[j]-mx)*inv;
}

__global__ void k_p0(const float* __restrict__ Wp0, const float* __restrict__ bp0){
    int gw = (blockIdx.x*blockDim.x + threadIdx.x) >> 5;
    int lane = threadIdx.x & 31;
    if (gw >= BT_) return;
    float a = 0.f;
    for (int k=lane; k<H_; k+=32) a = fmaf(d_tt[(size_t)gw*H_+k], Wp0[k], a);
    #pragma unroll
    for (int o=16;o>0;o>>=1) a += __shfl_xor_sync(0xffffffffu, a, o);
    if (lane==0) d_p0v[gw] = sigmf(a + bp0[0]);
}

__global__ void k_transition(float* __restrict__ out){
    int b = blockIdx.y;
    int idx = blockIdx.x*256 + threadIdx.x;     // over T*2T = 8192
    if (idx >= T_*2*T_) return;
    int i = idx / (2*T_), c = idx % (2*T_);
    float tv, lv;
    if (c < T_){
        float jw = d_jl[(size_t)(b*T_+i)*J_ + (MM_ + c - i)];
        tv = jw; lv = logf(jw);
    } else {
        int j = c - T_;
        float p = d_p0v[b*T_+i];
        tv = (i==j) ? p : 0.f;
        lv = (i==j) ? logf(p) : 0.f;
    }
    float* tr  = out + (size_t)B_*2*T_*S_ + (size_t)b*(2*T_*2*T_);
    float* trl = tr + (size_t)B_*2*T_*2*T_;
    tr [i*2*T_ + c] = tv;  tr [(T_+i)*2*T_ + c] = tv;
    trl[i*2*T_ + c] = lv;  trl[(T_+i)*2*T_ + c] = lv;
}

extern "C" void kernel_launch(void* const* d_in, const int* in_sizes, int n_in,
                              void* d_out, int out_size) {
    const int*   sources = (const int*)  d_in[0];
    const int*   targets = (const int*)  d_in[1];
    const int*   tnull   = (const int*)  d_in[2];
    const int*   lengths = (const int*)  d_in[3];
    const float* emb     = (const float*)d_in[4];
    const float* nnW     = (const float*)d_in[5];
    const float* nnb     = (const float*)d_in[6];
    const float* Wx_fw   = (const float*)d_in[7];
    const float* Wh_fw   = (const float*)d_in[8];
    const float* b_fw    = (const float*)d_in[9];
    const float* Wx_bw   = (const float*)d_in[10];
    const float* Wh_bw   = (const float*)d_in[11];
    const float* b_bw    = (const float*)d_in[12];
    const float* Wproj_e = (const float*)d_in[13];
    const float* Wv      = (const float*)d_in[14];
    const float* bv      = (const float*)d_in[15];
    const float* Wproj_t = (const float*)d_in[16];
    const float* Wj      = (const float*)d_in[17];
    const float* bj      = (const float*)d_in[18];
    const float* Wp0     = (const float*)d_in[19];
    const float* bp0     = (const float*)d_in[20];
    float* out = (float*)d_out;

    float *gfw, *gbw, *xp, *xrp, *hc, *tsp, *lg, *tmp, *ttp, *jl;
    cudaGetSymbolAddress((void**)&gfw, d_gpre_fw);
    cudaGetSymbolAddress((void**)&gbw, d_gpre_bw);
    cudaGetSymbolAddress((void**)&xp,  d_x);
    cudaGetSymbolAddress((void**)&xrp, d_xrev);
    cudaGetSymbolAddress((void**)&hc,  d_hcat);
    cudaGetSymbolAddress((void**)&tsp, d_ts);
    cudaGetSymbolAddress((void**)&lg,  d_logits);
    cudaGetSymbolAddress((void**)&tmp, d_tmpt);
    cudaGetSymbolAddress((void**)&ttp, d_tt);
    cudaGetSymbolAddress((void**)&jl,  d_jl);

    k_init<<<64,256>>>();
    k_embed<<<BT_,256>>>(targets, lengths, emb);
    k_nullstate<<<1,512>>>(tnull, emb, nnW, nnb);

    // input projections for all timesteps (fp32 — feeds the recurrence)
    sgemm_k<0><<<dim3(16,16),256>>>(xp,  Wx_fw, b_fw, gfw, BT_, G4_, E_);
    sgemm_k<0><<<dim3(16,16),256>>>(xrp, Wx_bw, b_bw, gbw, BT_, G4_, E_);

    for (int t = 0; t < T_; t++){
        k_lstm_gemm<<<dim3(16,2,4),256>>>(Wh_fw, Wh_bw);
        k_lstm_combine<<<dim3(B_,2),512>>>(lengths, t);
    }

    // emission path (tf32 tensor cores; M=1024, N mult of 128, K mult of 16)
    tf32gemm_k<<<dim3(8,4),256>>>(hc, Wproj_e, nullptr, tsp, BT_, H_, 2*H_);
    tf32gemm_k<<<dim3(8,250),256>>>(tsp, Wv, bv, lg, BT_, VS_, H_);
    k_rowreduce<<<BT_,256>>>();
    k_nulllogits<<<125,256>>>(Wv, bv);
    k_nullreduce<<<1,1024>>>();
    k_emission<<<BT_,64>>>(sources, out);

    // transition path (fp32, small)
    sgemm_k<0><<<dim3(2,16),256>>>(hc, Wproj_t, nullptr, tmp, BT_, E_, 2*H_);
    sgemm_k<1><<<dim3(4,16),256>>>(tmp, nnW, nnb, ttp, BT_, H_, E_);
    sgemm_k<0><<<dim3(2,16),256>>>(ttp, Wj, bj, jl, BT_, J_, H_);
    k_jsoftmax<<<BT_,256>>>();
    k_p0<<<128,256>>>(Wp0, bp0);
    k_transition<<<dim3(32,16),256>>>(out);
}

// round 9
// speedup vs baseline: 1.7007x; 1.0983x over previous
#include <cuda_runtime.h>
#include <cuda_bf16.h>
#include <cstdint>

#define B_  16
#define S_  64
#define T_  64
#define E_  256
#define H_  512
#define VS_ 32000
#define MM_ 100
#define J_  201
#define BT_ (B_*T_)
#define G4_ (4*H_)

__device__ float d_x[BT_*E_];
__device__ float d_xrev[BT_*E_];
__device__ float d_gpre_fw[BT_*G4_];
__device__ float d_gpre_bw[BT_*G4_];
__device__ float d_gpart[4*2*B_*G4_];
__device__ float d_hstate[2*B_*H_];
__device__ float d_cstate[2*B_*H_];
__device__ float d_hcat[BT_*2*H_];
__device__ float d_ts[BT_*H_];
__device__ float d_logits[(size_t)BT_*VS_];
__device__ float d_rowmax[BT_];
__device__ float d_rowsum[BT_];
__device__ float d_nullstate[H_];
__device__ float d_nulllog[VS_];
__device__ float d_nullred[2];
__device__ float d_tmpt[BT_*E_];
__device__ float d_tt[BT_*H_];
__device__ float d_jl[BT_*J_];
__device__ float d_p0v[BT_];
__device__ __nv_bfloat16 d_tsb[BT_*H_];
__device__ __nv_bfloat16 d_wvT[(size_t)VS_*H_];

__device__ __forceinline__ float sigmf(float x){ return 1.f/(1.f+expf(-x)); }
__device__ __forceinline__ uint32_t f2tf32(float v){
    uint32_t r; asm("cvt.rna.tf32.f32 %0, %1;" : "=r"(r) : "f"(v)); return r;
}

__global__ void k_init(){
    int i = blockIdx.x*blockDim.x + threadIdx.x;
    if (i < 2*B_*H_){ d_hstate[i]=0.f; d_cstate[i]=0.f; }
}

__global__ void k_embed(const int* __restrict__ targets, const int* __restrict__ lengths,
                        const float* __restrict__ emb){
    int bt = blockIdx.x, b = bt/T_, t = bt%T_;
    int len = lengths[b];
    int rt = (t < len) ? (len-1-t) : t;
    int r0 = targets[bt], r1 = targets[b*T_+rt];
    for (int e = threadIdx.x; e < E_; e += blockDim.x){
        d_x[bt*E_+e]    = emb[(size_t)r0*E_+e];
        d_xrev[bt*E_+e] = emb[(size_t)r1*E_+e];
    }
}

__global__ void k_nullstate(const int* __restrict__ tnull, const float* __restrict__ emb,
                            const float* __restrict__ nnW, const float* __restrict__ nnb){
    __shared__ float xe[E_];
    int tid = threadIdx.x;          // 512
    int r = tnull[0];
    for (int e = tid; e < E_; e += blockDim.x) xe[e] = emb[(size_t)r*E_+e];
    __syncthreads();
    float a = nnb[tid];
    #pragma unroll 4
    for (int e = 0; e < E_; e++) a = fmaf(xe[e], nnW[e*H_+tid], a);
    d_nullstate[tid] = tanhf(a);
}

// convert ts (fp32) -> bf16
__global__ void k_cvt_ts(){
    int i = blockIdx.x*blockDim.x + threadIdx.x;
    if (i < BT_*H_) d_tsb[i] = __float2bfloat16(d_ts[i]);
}

// transpose+convert Wv [H,VS] fp32 -> d_wvT [VS,H] bf16
__global__ void k_cvt_wvT(const float* __restrict__ Wv){
    __shared__ float tile[32][33];
    int nb = blockIdx.x, kb = blockIdx.y;
    int tx = threadIdx.x, ty = threadIdx.y;   // 32 x 8
    #pragma unroll
    for (int i = 0; i < 32; i += 8)
        tile[ty+i][tx] = Wv[(size_t)(kb*32+ty+i)*VS_ + nb*32+tx];
    __syncthreads();
    #pragma unroll
    for (int i = 0; i < 32; i += 8)
        d_wvT[(size_t)(nb*32+ty+i)*H_ + kb*32+tx] = __float2bfloat16(tile[tx][ty+i]);
}

// ---------------- bf16 mma.sync GEMM: C[M,N] = A[M,K] @ BT[N,K]^T + bias ----------------
// A row-major bf16, BT row-major bf16 (K contiguous). grid=(N/128, M/128), 256 thr.
// M,N multiples of 128; K multiple of 32.
__global__ void __launch_bounds__(256) bf16gemm_k(const __nv_bfloat16* __restrict__ A,
                                                  const __nv_bfloat16* __restrict__ BT,
                                                  const float* __restrict__ bias,
                                                  float* __restrict__ C,
                                                  int M, int N, int K)
{
    const int BK = 32, LDW = 40;          // 40 bf16 row stride (80 B) — conflict-free
    __shared__ __align__(16) __nv_bfloat16 As[128*LDW];
    __shared__ __align__(16) __nv_bfloat16 Bs[128*LDW];
    int tid = threadIdx.x, lane = tid & 31, wid = tid >> 5;
    int wm = wid & 3, wn = wid >> 2;       // warp tile 32(M) x 64(N)
    int gid = lane >> 2, tig = lane & 3;
    int col0 = blockIdx.x * 128, row0 = blockIdx.y * 128;

    float c[2][8][4];
    #pragma unroll
    for (int mt=0; mt<2; mt++){
        #pragma unroll
        for (int nt=0; nt<8; nt++){
            #pragma unroll
            for (int q=0; q<4; q++) c[mt][nt][q] = 0.f;
        }
    }

    for (int k0 = 0; k0 < K; k0 += BK){
        // stage A,B: 128 rows x 32 bf16 = 512 x 16B chunks each; 2 per thread
        #pragma unroll
        for (int j = 0; j < 2; j++){
            int s = tid*2 + j;
            int r = s >> 2, q8 = (s & 3)*8;
            *reinterpret_cast<uint4*>(&As[r*LDW + q8]) =
                *reinterpret_cast<const uint4*>(A + (size_t)(row0 + r)*K + k0 + q8);
        }
        #pragma unroll
        for (int j = 0; j < 2; j++){
            int s = tid*2 + j;
            int r = s >> 2, q8 = (s & 3)*8;
            *reinterpret_cast<uint4*>(&Bs[r*LDW + q8]) =
                *reinterpret_cast<const uint4*>(BT + (size_t)(col0 + r)*K + k0 + q8);
        }
        __syncthreads();
        #pragma unroll
        for (int kk = 0; kk < BK; kk += 16){
            uint32_t a[2][4], b[8][2];
            #pragma unroll
            for (int mt=0; mt<2; mt++){
                int r = (wm*32 + mt*16 + gid)*LDW;
                a[mt][0] = *reinterpret_cast<const uint32_t*>(&As[r            + kk + 2*tig]);
                a[mt][1] = *reinterpret_cast<const uint32_t*>(&As[r + 8*LDW    + kk + 2*tig]);
                a[mt][2] = *reinterpret_cast<const uint32_t*>(&As[r            + kk + 8 + 2*tig]);
                a[mt][3] = *reinterpret_cast<const uint32_t*>(&As[r + 8*LDW    + kk + 8 + 2*tig]);
            }
            #pragma unroll
            for (int nt=0; nt<8; nt++){
                int r = (wn*64 + nt*8 + gid)*LDW;
                b[nt][0] = *reinterpret_cast<const uint32_t*>(&Bs[r + kk + 2*tig]);
                b[nt][1] = *reinterpret_cast<const uint32_t*>(&Bs[r + kk + 8 + 2*tig]);
            }
            #pragma unroll
            for (int mt=0; mt<2; mt++){
                #pragma unroll
                for (int nt=0; nt<8; nt++)
                    asm("mma.sync.aligned.m16n8k16.row.col.f32.bf16.bf16.f32 "
                        "{%0,%1,%2,%3}, {%4,%5,%6,%7}, {%8,%9}, {%0,%1,%2,%3};"
                        : "+f"(c[mt][nt][0]), "+f"(c[mt][nt][1]),
                          "+f"(c[mt][nt][2]), "+f"(c[mt][nt][3])
                        : "r"(a[mt][0]), "r"(a[mt][1]), "r"(a[mt][2]), "r"(a[mt][3]),
                          "r"(b[nt][0]), "r"(b[nt][1]));
            }
        }
        __syncthreads();
    }
    #pragma unroll
    for (int mt=0; mt<2; mt++){
        int r = row0 + wm*32 + mt*16 + gid;
        #pragma unroll
        for (int nt=0; nt<8; nt++){
            int cc = col0 + wn*64 + nt*8 + tig*2;
            float b0 = bias ? bias[cc] : 0.f;
            float b1 = bias ? bias[cc+1] : 0.f;
            C[(size_t)r*N + cc]       = c[mt][nt][0] + b0;
            C[(size_t)r*N + cc + 1]   = c[mt][nt][1] + b1;
            C[(size_t)(r+8)*N + cc]   = c[mt][nt][2] + b0;
            C[(size_t)(r+8)*N + cc+1] = c[mt][nt][3] + b1;
        }
    }
}

// ---------------- tf32 tensor-core GEMM (mma.sync; used for proj_e) ----------------
__global__ void tf32gemm_k(const float* __restrict__ A, const float* __restrict__ Bm,
                           const float* __restrict__ bias, float* __restrict__ C,
                           int M, int N, int K)
{
    __shared__ float As[16][132];
    __shared__ float Bs[16][132];
    int tid = threadIdx.x, lane = tid & 31, wid = tid >> 5;
    int wm = wid & 3, wn = wid >> 2;
    int gid = lane >> 2, tig = lane & 3;
    int row0 = blockIdx.x * 128, col0 = blockIdx.y * 128;

    float c[2][8][4];
    #pragma unroll
    for (int mt=0; mt<2; mt++){
        #pragma unroll
        for (int nt=0; nt<8; nt++){
            #pragma unroll
            for (int q=0; q<4; q++) c[mt][nt][q] = 0.f;
        }
    }

    for (int k0 = 0; k0 < K; k0 += 16){
        #pragma unroll
        for (int j = 0; j < 2; j++){
            int s = tid*2 + j;
            int r = s >> 2, kq = (s & 3)*4;
            float4 v = *reinterpret_cast<const float4*>(&A[(size_t)(row0 + r)*K + k0 + kq]);
            As[kq+0][r] = __uint_as_float(f2tf32(v.x));
            As[kq+1][r] = __uint_as_float(f2tf32(v.y));
            As[kq+2][r] = __uint_as_float(f2tf32(v.z));
            As[kq+3][r] = __uint_as_float(f2tf32(v.w));
        }
        #pragma unroll
        for (int j = 0; j < 2; j++){
            int s = tid*2 + j;
            int r = s >> 5, c4 = (s & 31)*4;
            float4 v = *reinterpret_cast<const float4*>(&Bm[(size_t)(k0 + r)*N + col0 + c4]);
            Bs[r][c4+0] = __uint_as_float(f2tf32(v.x));
            Bs[r][c4+1] = __uint_as_float(f2tf32(v.y));
            Bs[r][c4+2] = __uint_as_float(f2tf32(v.z));
            Bs[r][c4+3] = __uint_as_float(f2tf32(v.w));
        }
        __syncthreads();
        #pragma unroll
        for (int kk = 0; kk < 2; kk++){
            int kb = kk*8;
            uint32_t a[2][4], b[8][2];
            #pragma unroll
            for (int mt=0; mt<2; mt++){
                int r = wm*32 + mt*16 + gid;
                a[mt][0] = __float_as_uint(As[kb+tig  ][r  ]);
                a[mt][1] = __float_as_uint(As[kb+tig  ][r+8]);
                a[mt][2] = __float_as_uint(As[kb+tig+4][r  ]);
                a[mt][3] = __float_as_uint(As[kb+tig+4][r+8]);
            }
            #pragma unroll
            for (int nt=0; nt<8; nt++){
                int n = wn*64 + nt*8 + gid;
                b[nt][0] = __float_as_uint(Bs[kb+tig  ][n]);
                b[nt][1] = __float_as_uint(Bs[kb+tig+4][n]);
            }
            #pragma unroll
            for (int mt=0; mt<2; mt++){
                #pragma unroll
                for (int nt=0; nt<8; nt++)
                    asm("mma.sync.aligned.m16n8k8.row.col.f32.tf32.tf32.f32 "
                        "{%0,%1,%2,%3}, {%4,%5,%6,%7}, {%8,%9}, {%0,%1,%2,%3};"
                        : "+f"(c[mt][nt][0]), "+f"(c[mt][nt][1]),
                          "+f"(c[mt][nt][2]), "+f"(c[mt][nt][3])
                        : "r"(a[mt][0]), "r"(a[mt][1]), "r"(a[mt][2]), "r"(a[mt][3]),
                          "r"(b[nt][0]), "r"(b[nt][1]));
            }
        }
        __syncthreads();
    }
    #pragma unroll
    for (int mt=0; mt<2; mt++){
        int r = row0 + wm*32 + mt*16 + gid;
        #pragma unroll
        for (int nt=0; nt<8; nt++){
            int cc = col0 + wn*64 + nt*8 + tig*2;
            float b0 = bias ? bias[cc] : 0.f;
            float b1 = bias ? bias[cc+1] : 0.f;
            C[(size_t)r*N + cc]       = c[mt][nt][0] + b0;
            C[(size_t)r*N + cc + 1]   = c[mt][nt][1] + b1;
            C[(size_t)(r+8)*N + cc]   = c[mt][nt][2] + b0;
            C[(size_t)(r+8)*N + cc+1] = c[mt][nt][3] + b1;
        }
    }
}

// tiled SGEMM, packed f32x2 FMA. C = A[MxK] @ B[KxN] (+bias) (+tanh if ACT)
template<int ACT>
__global__ void sgemm_k(const float* __restrict__ A, const float* __restrict__ Bm,
                        const float* __restrict__ bias, float* __restrict__ C,
                        int M, int N, int K)
{
    const int BM=64, BN=128, BK=16, TM=4, TN=8, THREADS=256;
    __shared__ float As[BM][BK+1];
    __shared__ __align__(16) float Bs[BK][BN];
    int tid = threadIdx.x;
    int tx = tid % (BN/TN), ty = tid / (BN/TN);
    int row0 = blockIdx.y*BM, col0 = blockIdx.x*BN;
    unsigned long long acc2[TM][TN/2];
    #pragma unroll
    for (int m=0;m<TM;m++){
        #pragma unroll
        for (int i=0;i<TN/2;i++) acc2[m][i]=0ull;
    }
    for (int k0 = 0; k0 < K; k0 += BK){
        for (int l = tid; l < BM*BK; l += THREADS){
            int r=l/BK, c=l%BK;
            As[r][c] = A[(size_t)(row0+r)*K + k0 + c];
        }
        for (int l = tid; l < BK*BN; l += THREADS){
            int r=l/BN, c=l%BN, gc=col0+c;
            Bs[r][c] = (gc<N) ? Bm[(size_t)(k0+r)*N + gc] : 0.f;
        }
        __syncthreads();
        #pragma unroll
        for (int kk=0; kk<BK; kk++){
            unsigned long long b2[TN/2];
            #pragma unroll
            for (int i=0;i<TN/2;i++)
                b2[i] = *reinterpret_cast<const unsigned long long*>(&Bs[kk][tx*TN+2*i]);
            #pragma unroll
            for (int m=0;m<TM;m++){
                float av = As[ty*TM+m][kk];
                unsigned long long a2;
                asm("mov.b64 %0, {%1, %1};" : "=l"(a2) : "r"(__float_as_uint(av)));
                #pragma unroll
                for (int i=0;i<TN/2;i++)
                    asm("fma.rn.f32x2 %0, %1, %2, %0;" : "+l"(acc2[m][i]) : "l"(a2), "l"(b2[i]));
            }
        }
        __syncthreads();
    }
    #pragma unroll
    for (int m=0;m<TM;m++){
        int gr = row0 + ty*TM + m;
        #pragma unroll
        for (int i=0;i<TN/2;i++){
            unsigned lo,hi;
            asm("mov.b64 {%0, %1}, %2;" : "=r"(lo), "=r"(hi) : "l"(acc2[m][i]));
            int gc0 = col0 + tx*TN + 2*i;
            if (gc0 < N){
                float v = __uint_as_float(lo);
                if (bias) v += bias[gc0];
                if (ACT) v = tanhf(v);
                C[(size_t)gr*N + gc0] = v;
            }
            if (gc0+1 < N){
                float v = __uint_as_float(hi);
                if (bias) v += bias[gc0+1];
                if (ACT) v = tanhf(v);
                C[(size_t)gr*N + gc0+1] = v;
            }
        }
    }
}

// recurrent GEMM: gpart[ks,dir,b,4H] = h_prev[dir,b,:]@Wh[dir] (split-K x4)
__global__ void k_lstm_gemm(const float* __restrict__ Wh_fw, const float* __restrict__ Wh_bw){
    int chunk = blockIdx.x, dir = blockIdx.y, ks = blockIdx.z;
    int tid = threadIdx.x;
    int colid = tid & 127, bg = tid >> 7;
    __shared__ __align__(16) float hsT[128*16];   // [k][b]
    const float* hprev = d_hstate + dir*(B_*H_);
    for (int i = tid; i < 128*16; i += 256){
        int k = i>>4, b = i&15;
        hsT[i] = hprev[b*H_ + ks*128 + k];
    }
    __syncthreads();
    const float* Wh = dir ? Wh_bw : Wh_fw;
    int colg = chunk*128 + colid;
    const float* wp = Wh + (size_t)(ks*128)*G4_ + colg;
    unsigned long long acc2[4] = {0,0,0,0};
    #pragma unroll 4
    for (int k = 0; k < 128; k++){
        float w = wp[(size_t)k*G4_];
        unsigned long long w2;
        asm("mov.b64 %0, {%1, %1};" : "=l"(w2) : "r"(__float_as_uint(w)));
        const unsigned long long* hv = reinterpret_cast<const unsigned long long*>(&hsT[k*16 + bg*8]);
        #pragma unroll
        for (int j=0;j<4;j++)
            asm("fma.rn.f32x2 %0, %1, %2, %0;" : "+l"(acc2[j]) : "l"(hv[j]), "l"(w2));
    }
    float* gp = d_gpart + ((size_t)(ks*2+dir)*B_ + bg*8)*G4_ + colg;
    #pragma unroll
    for (int j=0;j<4;j++){
        unsigned lo,hi;
        asm("mov.b64 {%0, %1}, %2;" : "=r"(lo), "=r"(hi) : "l"(acc2[j]));
        gp[(size_t)(2*j)*G4_]   = __uint_as_float(lo);
        gp[(size_t)(2*j+1)*G4_] = __uint_as_float(hi);
    }
}

__global__ void k_lstm_combine(const int* __restrict__ lengths, int t){
    int b = blockIdx.x, dir = blockIdx.y, h = threadIdx.x;   // 512
    const float* gp = (dir ? d_gpre_bw : d_gpre_fw) + (size_t)(b*T_+t)*G4_;
    float g[4];
    #pragma unroll
    for (int gt=0; gt<4; gt++){
        float a = gp[gt*H_+h];
        #pragma unroll
        for (int ks=0; ks<4; ks++)
            a += d_gpart[((size_t)(ks*2+dir)*B_ + b)*G4_ + gt*H_ + h];
        g[gt] = a;
    }
    int idx = (dir*B_+b)*H_+h;
    float c = d_cstate[idx], hp = d_hstate[idx];
    float cn = sigmf(g[2]+1.f)*c + sigmf(g[0])*tanhf(g[1]);
    float hn = sigmf(g[3])*tanhf(cn);
    int len = lengths[b];
    bool m = (t < len);
    d_cstate[idx] = m ? cn : c;
    d_hstate[idx] = m ? hn : hp;
    float ho = m ? hn : 0.f;
    if (dir == 0) d_hcat[(size_t)(b*T_+t)*(2*H_) + h] = ho;
    else { int p = m ? (len-1-t) : t; d_hcat[(size_t)(b*T_+p)*(2*H_) + H_ + h] = ho; }
}

__global__ void k_rowreduce(){
    int row = blockIdx.x, tid = threadIdx.x;
    const float* p = d_logits + (size_t)row*VS_;
    __shared__ float sm[256];
    float m = -1e30f;
    for (int v=tid; v<VS_; v+=256) m = fmaxf(m, p[v]);
    sm[tid]=m; __syncthreads();
    for (int s=128;s>0;s>>=1){ if(tid<s) sm[tid]=fmaxf(sm[tid],sm[tid+s]); __syncthreads(); }
    float mx = sm[0]; __syncthreads();
    float su = 0.f;
    for (int v=tid; v<VS_; v+=256) su += expf(p[v]-mx);
    sm[tid]=su; __syncthreads();
    for (int s=128;s>0;s>>=1){ if(tid<s) sm[tid]+=sm[tid+s]; __syncthreads(); }
    if (tid==0){ d_rowmax[row]=mx; d_rowsum[row]=sm[0]; }
}

__global__ void k_nulllogits(const float* __restrict__ Wv, const float* __restrict__ bv){
    __shared__ float ns[H_];
    int tid = threadIdx.x;
    for (int k=tid; k<H_; k+=256) ns[k] = d_nullstate[k];
    __syncthreads();
    int v = blockIdx.x*256 + tid;
    if (v < VS_){
        float a = bv[v];
        #pragma unroll 4
        for (int k=0;k<H_;k++) a = fmaf(ns[k], Wv[(size_t)k*VS_+v], a);
        d_nulllog[v] = a;
    }
}

__global__ void k_nullreduce(){
    __shared__ float sm[1024];
    int tid = threadIdx.x;
    float m = -1e30f;
    for (int v=tid; v<VS_; v+=1024) m = fmaxf(m, d_nulllog[v]);
    sm[tid]=m; __syncthreads();
    for (int s=512;s>0;s>>=1){ if(tid<s) sm[tid]=fmaxf(sm[tid],sm[tid+s]); __syncthreads(); }
    float mx = sm[0]; __syncthreads();
    float su = 0.f;
    for (int v=tid; v<VS_; v+=1024) su += expf(d_nulllog[v]-mx);
    sm[tid]=su; __syncthreads();
    for (int s=512;s>0;s>>=1){ if(tid<s) sm[tid]+=sm[tid+s]; __syncthreads(); }
    if (tid==0){ d_nullred[0]=mx; d_nullred[1]=sm[0]; }
}

__global__ void k_emission(const int* __restrict__ sources, float* __restrict__ out){
    int bt = blockIdx.x, b = bt>>6, t = bt&63, s = threadIdx.x;   // 64
    int col = sources[b*S_+s];
    float l = d_logits[(size_t)bt*VS_ + col];
    out[(size_t)b*(2*T_*S_) + t*S_ + s] = expf(l - d_rowmax[bt]) / d_rowsum[bt];
    out[(size_t)b*(2*T_*S_) + (T_+t)*S_ + s] = expf(d_nulllog[col]-d_nullred[0]) / d_nullred[1];
}

__global__ void k_jsoftmax(){
    int row = blockIdx.x, tid = threadIdx.x;
    float* p = d_jl + (size_t)row*J_;
    __shared__ float sm[256];
    float m = -1e30f;
    for (int j=tid; j<J_; j+=256) m = fmaxf(m, p[j]);
    sm[tid]=m; __syncthreads();
    for (int s=128;s>0;s>>=1){ if(tid<s) sm[tid]=fmaxf(sm[tid],sm[tid+s]); __syncthreads(); }
    float mx = sm[0]; __syncthreads();
    float su = 0.f;
    for (int j=tid; j<J_; j+=256) su += expf(p[j]-mx);
    sm[tid]=su; __syncthreads();
    for (int s=128;s>0;s>>=1){ if(tid<s) sm[tid]+=sm[tid+s]; __syncthreads(); }
    float inv = 1.f/sm[0]; __syncthreads();
    for (int j=tid; j<J_; j+=256) p[j] = expf(p[j]-mx)*inv;
}

__global__ void k_p0(const float* __restrict__ Wp0, const float* __restrict__ bp0){
    int gw = (blockIdx.x*blockDim.x + threadIdx.x) >> 5;
    int lane = threadIdx.x & 31;
    if (gw >= BT_) return;
    float a = 0.f;
    for (int k=lane; k<H_; k+=32) a = fmaf(d_tt[(size_t)gw*H_+k], Wp0[k], a);
    #pragma unroll
    for (int o=16;o>0;o>>=1) a += __shfl_xor_sync(0xffffffffu, a, o);
    if (lane==0) d_p0v[gw] = sigmf(a + bp0[0]);
}

__global__ void k_transition(float* __restrict__ out){
    int b = blockIdx.y;
    int idx = blockIdx.x*256 + threadIdx.x;     // over T*2T = 8192
    if (idx >= T_*2*T_) return;
    int i = idx / (2*T_), c = idx % (2*T_);
    float tv, lv;
    if (c < T_){
        float jw = d_jl[(size_t)(b*T_+i)*J_ + (MM_ + c - i)];
        tv = jw; lv = logf(jw);
    } else {
        int j = c - T_;
        float p = d_p0v[b*T_+i];
        tv = (i==j) ? p : 0.f;
        lv = (i==j) ? logf(p) : 0.f;
    }
    float* tr  = out + (size_t)B_*2*T_*S_ + (size_t)b*(2*T_*2*T_);
    float* trl = tr + (size_t)B_*2*T_*2*T_;
    tr [i*2*T_ + c] = tv;  tr [(T_+i)*2*T_ + c] = tv;
    trl[i*2*T_ + c] = lv;  trl[(T_+i)*2*T_ + c] = lv;
}

extern "C" void kernel_launch(void* const* d_in, const int* in_sizes, int n_in,
                              void* d_out, int out_size) {
    const int*   sources = (const int*)  d_in[0];
    const int*   targets = (const int*)  d_in[1];
    const int*   tnull   = (const int*)  d_in[2];
    const int*   lengths = (const int*)  d_in[3];
    const float* emb     = (const float*)d_in[4];
    const float* nnW     = (const float*)d_in[5];
    const float* nnb     = (const float*)d_in[6];
    const float* Wx_fw   = (const float*)d_in[7];
    const float* Wh_fw   = (const float*)d_in[8];
    const float* b_fw    = (const float*)d_in[9];
    const float* Wx_bw   = (const float*)d_in[10];
    const float* Wh_bw   = (const float*)d_in[11];
    const float* b_bw    = (const float*)d_in[12];
    const float* Wproj_e = (const float*)d_in[13];
    const float* Wv      = (const float*)d_in[14];
    const float* bv      = (const float*)d_in[15];
    const float* Wproj_t = (const float*)d_in[16];
    const float* Wj      = (const float*)d_in[17];
    const float* bj      = (const float*)d_in[18];
    const float* Wp0     = (const float*)d_in[19];
    const float* bp0     = (const float*)d_in[20];
    float* out = (float*)d_out;

    float *gfw, *gbw, *xp, *xrp, *hc, *tsp, *lg, *tmp, *ttp, *jl;
    __nv_bfloat16 *tsb, *wvT;
    cudaGetSymbolAddress((void**)&gfw, d_gpre_fw);
    cudaGetSymbolAddress((void**)&gbw, d_gpre_bw);
    cudaGetSymbolAddress((void**)&xp,  d_x);
    cudaGetSymbolAddress((void**)&xrp, d_xrev);
    cudaGetSymbolAddress((void**)&hc,  d_hcat);
    cudaGetSymbolAddress((void**)&tsp, d_ts);
    cudaGetSymbolAddress((void**)&lg,  d_logits);
    cudaGetSymbolAddress((void**)&tmp, d_tmpt);
    cudaGetSymbolAddress((void**)&ttp, d_tt);
    cudaGetSymbolAddress((void**)&jl,  d_jl);
    cudaGetSymbolAddress((void**)&tsb, d_tsb);
    cudaGetSymbolAddress((void**)&wvT, d_wvT);

    k_init<<<64,256>>>();
    k_embed<<<BT_,256>>>(targets, lengths, emb);
    k_nullstate<<<1,512>>>(tnull, emb, nnW, nnb);
    k_cvt_wvT<<<dim3(1000,16),dim3(32,8)>>>(Wv);

    // input projections for all timesteps (fp32 — feeds the recurrence)
    sgemm_k<0><<<dim3(16,16),256>>>(xp,  Wx_fw, b_fw, gfw, BT_, G4_, E_);
    sgemm_k<0><<<dim3(16,16),256>>>(xrp, Wx_bw, b_bw, gbw, BT_, G4_, E_);

    for (int t = 0; t < T_; t++){
        k_lstm_gemm<<<dim3(16,2,4),256>>>(Wh_fw, Wh_bw);
        k_lstm_combine<<<dim3(B_,2),512>>>(lengths, t);
    }

    // emission path: proj_e on tf32 mma.sync, logits on bf16 mma.sync
    tf32gemm_k<<<dim3(8,4),256>>>(hc, Wproj_e, nullptr, tsp, BT_, H_, 2*H_);
    k_cvt_ts<<<(BT_*H_+255)/256,256>>>();
    bf16gemm_k<<<dim3(250,8),256>>>(tsb, wvT, bv, lg, BT_, VS_, H_);
    k_rowreduce<<<BT_,256>>>();
    k_nulllogits<<<125,256>>>(Wv, bv);
    k_nullreduce<<<1,1024>>>();
    k_emission<<<BT_,64>>>(sources, out);

    // transition path (fp32, small)
    sgemm_k<0><<<dim3(2,16),256>>>(hc, Wproj_t, nullptr, tmp, BT_, E_, 2*H_);
    sgemm_k<1><<<dim3(4,16),256>>>(tmp, nnW, nnb, ttp, BT_, H_, E_);
    sgemm_k<0><<<dim3(2,16),256>>>(ttp, Wj, bj, jl, BT_, J_, H_);
    k_jsoftmax<<<BT_,256>>>();
    k_p0<<<128,256>>>(Wp0, bp0);
    k_transition<<<dim3(32,16),256>>>(out);
}

// round 10
// speedup vs baseline: 1.7413x; 1.0239x over previous
#include <cuda_runtime.h>
#include <cuda_bf16.h>
#include <cstdint>

#define B_  16
#define S_  64
#define T_  64
#define E_  256
#define H_  512
#define VS_ 32000
#define MM_ 100
#define J_  201
#define BT_ (B_*T_)
#define G4_ (4*H_)

__device__ float d_x[BT_*E_];
__device__ float d_xrev[BT_*E_];
__device__ float d_gpre_fw[BT_*G4_];
__device__ float d_gpre_bw[BT_*G4_];
__device__ float d_gpart[4*2*B_*G4_];
__device__ float d_hstate[2*B_*H_];
__device__ float d_cstate[2*B_*H_];
__device__ float d_hcat[BT_*2*H_];
__device__ float d_logits[(size_t)BT_*VS_];
__device__ float d_rowmax[BT_];
__device__ float d_rowsum[BT_];
__device__ float d_nullstate[H_];
__device__ float d_nulllog[VS_];
__device__ float d_nullred[2];
__device__ float d_tmpt[BT_*E_];
__device__ float d_tt[BT_*H_];
__device__ float d_jl[BT_*J_];
__device__ float d_p0v[BT_];
__device__ __nv_bfloat16 d_tsb[BT_*H_];
__device__ __nv_bfloat16 d_wvT[(size_t)VS_*H_];

__device__ __forceinline__ float sigmf(float x){ return 1.f/(1.f+expf(-x)); }
__device__ __forceinline__ uint32_t f2tf32(float v){
    uint32_t r; asm("cvt.rna.tf32.f32 %0, %1;" : "=r"(r) : "f"(v)); return r;
}

__global__ void k_init(){
    int i = blockIdx.x*blockDim.x + threadIdx.x;
    if (i < 2*B_*H_){ d_hstate[i]=0.f; d_cstate[i]=0.f; }
}

__global__ void k_embed(const int* __restrict__ targets, const int* __restrict__ lengths,
                        const float* __restrict__ emb){
    int bt = blockIdx.x, b = bt/T_, t = bt%T_;
    int len = lengths[b];
    int rt = (t < len) ? (len-1-t) : t;
    int r0 = targets[bt], r1 = targets[b*T_+rt];
    for (int e = threadIdx.x; e < E_; e += blockDim.x){
        d_x[bt*E_+e]    = emb[(size_t)r0*E_+e];
        d_xrev[bt*E_+e] = emb[(size_t)r1*E_+e];
    }
}

__global__ void k_nullstate(const int* __restrict__ tnull, const float* __restrict__ emb,
                            const float* __restrict__ nnW, const float* __restrict__ nnb){
    __shared__ float xe[E_];
    int tid = threadIdx.x;          // 512
    int r = tnull[0];
    for (int e = tid; e < E_; e += blockDim.x) xe[e] = emb[(size_t)r*E_+e];
    __syncthreads();
    float a = nnb[tid];
    #pragma unroll 4
    for (int e = 0; e < E_; e++) a = fmaf(xe[e], nnW[e*H_+tid], a);
    d_nullstate[tid] = tanhf(a);
}

// transpose+convert Wv [H,VS] fp32 -> d_wvT [VS,H] bf16
__global__ void k_cvt_wvT(const float* __restrict__ Wv){
    __shared__ float tile[32][33];
    int nb = blockIdx.x, kb = blockIdx.y;
    int tx = threadIdx.x, ty = threadIdx.y;   // 32 x 8
    #pragma unroll
    for (int i = 0; i < 32; i += 8)
        tile[ty+i][tx] = Wv[(size_t)(kb*32+ty+i)*VS_ + nb*32+tx];
    __syncthreads();
    #pragma unroll
    for (int i = 0; i < 32; i += 8)
        d_wvT[(size_t)(nb*32+ty+i)*H_ + kb*32+tx] = __float2bfloat16(tile[tx][ty+i]);
}

#define CP_ASYNC16(dst, src) \
    asm volatile("cp.async.cg.shared.global [%0], [%1], 16;\n" :: "r"(dst), "l"(src))
#define CP_COMMIT() asm volatile("cp.async.commit_group;\n" ::: "memory")
#define CP_WAIT(n)  asm volatile("cp.async.wait_group %0;\n" :: "n"(n) : "memory")

// ---------------- bf16 mma.sync GEMM with ldmatrix + cp.async double buffer ----------------
// C[M,N] = A[M,K] @ BT[N,K]^T + bias. grid=(M/128, N/128) — x=M so consecutive
// CTAs share the BT tile in L2. 256 threads. K multiple of 32.
__global__ void __launch_bounds__(256) bf16gemm_k(const __nv_bfloat16* __restrict__ A,
                                                  const __nv_bfloat16* __restrict__ BT,
                                                  const float* __restrict__ bias,
                                                  float* __restrict__ C,
                                                  int M, int N, int K)
{
    const int BK = 32, LDW = 40;
    __shared__ __align__(16) __nv_bfloat16 As[2][128*LDW];
    __shared__ __align__(16) __nv_bfloat16 Bs[2][128*LDW];
    int tid = threadIdx.x, lane = tid & 31, wid = tid >> 5;
    int wm = wid & 3, wn = wid >> 2;       // warp tile 32(M) x 64(N)
    int gid = lane >> 2, tig = lane & 3;
    int row0 = blockIdx.x * 128, col0 = blockIdx.y * 128;
    uint32_t sA = (uint32_t)__cvta_generic_to_shared(&As[0][0]);
    uint32_t sB = (uint32_t)__cvta_generic_to_shared(&Bs[0][0]);
    const uint32_t STG = 128*LDW*2;        // stage stride bytes

    // per-thread staging slots: 2 x 16B for A, 2 x 16B for B
    int r0s = (tid*2) >> 2, q0 = ((tid*2) & 3)*8;
    int r1s = (tid*2+1) >> 2, q1 = ((tid*2+1) & 3)*8;

    float c[2][8][4];
    #pragma unroll
    for (int mt=0; mt<2; mt++){
        #pragma unroll
        for (int nt=0; nt<8; nt++){
            #pragma unroll
            for (int q=0; q<4; q++) c[mt][nt][q] = 0.f;
        }
    }

    int nch = K / BK;
    // prologue: stage 0
    {
        CP_ASYNC16(sA + (uint32_t)(r0s*LDW + q0)*2, A + (size_t)(row0 + r0s)*K + q0);
        CP_ASYNC16(sA + (uint32_t)(r1s*LDW + q1)*2, A + (size_t)(row0 + r1s)*K + q1);
        CP_ASYNC16(sB + (uint32_t)(r0s*LDW + q0)*2, BT + (size_t)(col0 + r0s)*K + q0);
        CP_ASYNC16(sB + (uint32_t)(r1s*LDW + q1)*2, BT + (size_t)(col0 + r1s)*K + q1);
        CP_COMMIT();
    }
    // ldmatrix lane addressing
    int lq = lane >> 3, lr = lane & 7;     // matrix index, row-in-matrix

    for (int kc = 0; kc < nch; kc++){
        int cur = kc & 1;
        if (kc + 1 < nch){
            int nxt = (kc+1) & 1;
            int k0 = (kc+1)*BK;
            CP_ASYNC16(sA + nxt*STG + (uint32_t)(r0s*LDW + q0)*2, A + (size_t)(row0 + r0s)*K + k0 + q0);
            CP_ASYNC16(sA + nxt*STG + (uint32_t)(r1s*LDW + q1)*2, A + (size_t)(row0 + r1s)*K + k0 + q1);
            CP_ASYNC16(sB + nxt*STG + (uint32_t)(r0s*LDW + q0)*2, BT + (size_t)(col0 + r0s)*K + k0 + q0);
            CP_ASYNC16(sB + nxt*STG + (uint32_t)(r1s*LDW + q1)*2, BT + (size_t)(col0 + r1s)*K + k0 + q1);
            CP_COMMIT();
            CP_WAIT(1);
        } else {
            CP_WAIT(0);
        }
        __syncthreads();
        uint32_t baseA = sA + cur*STG, baseB = sB + cur*STG;
        #pragma unroll
        for (int kk = 0; kk < BK; kk += 16){
            uint32_t a[2][4], b[8][2];
            #pragma unroll
            for (int mt=0; mt<2; mt++){
                int row = wm*32 + mt*16 + (lq&1)*8 + lr;
                int col = kk + (lq>>1)*8;
                uint32_t addr = baseA + (uint32_t)(row*LDW + col)*2;
                asm volatile("ldmatrix.sync.aligned.m8n8.x4.shared.b16 {%0,%1,%2,%3}, [%4];"
                    : "=r"(a[mt][0]), "=r"(a[mt][1]), "=r"(a[mt][2]), "=r"(a[mt][3]) : "r"(addr));
            }
            #pragma unroll
            for (int p=0; p<4; p++){
                int row = wn*64 + p*16 + (lq&1)*8 + lr;
                int col = kk + (lq>>1)*8;
                uint32_t addr = baseB + (uint32_t)(row*LDW + col)*2;
                asm volatile("ldmatrix.sync.aligned.m8n8.x4.shared.b16 {%0,%1,%2,%3}, [%4];"
                    : "=r"(b[2*p][0]), "=r"(b[2*p+1][0]), "=r"(b[2*p][1]), "=r"(b[2*p+1][1]) : "r"(addr));
            }
            #pragma unroll
            for (int mt=0; mt<2; mt++){
                #pragma unroll
                for (int nt=0; nt<8; nt++)
                    asm("mma.sync.aligned.m16n8k16.row.col.f32.bf16.bf16.f32 "
                        "{%0,%1,%2,%3}, {%4,%5,%6,%7}, {%8,%9}, {%0,%1,%2,%3};"
                        : "+f"(c[mt][nt][0]), "+f"(c[mt][nt][1]),
                          "+f"(c[mt][nt][2]), "+f"(c[mt][nt][3])
                        : "r"(a[mt][0]), "r"(a[mt][1]), "r"(a[mt][2]), "r"(a[mt][3]),
                          "r"(b[nt][0]), "r"(b[nt][1]));
            }
        }
        __syncthreads();
    }
    #pragma unroll
    for (int mt=0; mt<2; mt++){
        int r = row0 + wm*32 + mt*16 + gid;
        #pragma unroll
        for (int nt=0; nt<8; nt++){
            int cc = col0 + wn*64 + nt*8 + tig*2;
            float b0 = bias ? bias[cc] : 0.f;
            float b1 = bias ? bias[cc+1] : 0.f;
            C[(size_t)r*N + cc]       = c[mt][nt][0] + b0;
            C[(size_t)r*N + cc + 1]   = c[mt][nt][1] + b1;
            C[(size_t)(r+8)*N + cc]   = c[mt][nt][2] + b0;
            C[(size_t)(r+8)*N + cc+1] = c[mt][nt][3] + b1;
        }
    }
}

// ---------------- tf32 mma.sync GEMM, bf16 output (proj_e) ----------------
__global__ void tf32gemm_bf16o_k(const float* __restrict__ A, const float* __restrict__ Bm,
                                 __nv_bfloat16* __restrict__ Cb, int M, int N, int K)
{
    __shared__ float As[16][132];
    __shared__ float Bs[16][132];
    int tid = threadIdx.x, lane = tid & 31, wid = tid >> 5;
    int wm = wid & 3, wn = wid >> 2;
    int gid = lane >> 2, tig = lane & 3;
    int row0 = blockIdx.x * 128, col0 = blockIdx.y * 128;

    float c[2][8][4];
    #pragma unroll
    for (int mt=0; mt<2; mt++){
        #pragma unroll
        for (int nt=0; nt<8; nt++){
            #pragma unroll
            for (int q=0; q<4; q++) c[mt][nt][q] = 0.f;
        }
    }

    for (int k0 = 0; k0 < K; k0 += 16){
        #pragma unroll
        for (int j = 0; j < 2; j++){
            int s = tid*2 + j;
            int r = s >> 2, kq = (s & 3)*4;
            float4 v = *reinterpret_cast<const float4*>(&A[(size_t)(row0 + r)*K + k0 + kq]);
            As[kq+0][r] = __uint_as_float(f2tf32(v.x));
            As[kq+1][r] = __uint_as_float(f2tf32(v.y));
            As[kq+2][r] = __uint_as_float(f2tf32(v.z));
            As[kq+3][r] = __uint_as_float(f2tf32(v.w));
        }
        #pragma unroll
        for (int j = 0; j < 2; j++){
            int s = tid*2 + j;
            int r = s >> 5, c4 = (s & 31)*4;
            float4 v = *reinterpret_cast<const float4*>(&Bm[(size_t)(k0 + r)*N + col0 + c4]);
            Bs[r][c4+0] = __uint_as_float(f2tf32(v.x));
            Bs[r][c4+1] = __uint_as_float(f2tf32(v.y));
            Bs[r][c4+2] = __uint_as_float(f2tf32(v.z));
            Bs[r][c4+3] = __uint_as_float(f2tf32(v.w));
        }
        __syncthreads();
        #pragma unroll
        for (int kk = 0; kk < 2; kk++){
            int kb = kk*8;
            uint32_t a[2][4], b[8][2];
            #pragma unroll
            for (int mt=0; mt<2; mt++){
                int r = wm*32 + mt*16 + gid;
                a[mt][0] = __float_as_uint(As[kb+tig  ][r  ]);
                a[mt][1] = __float_as_uint(As[kb+tig  ][r+8]);
                a[mt][2] = __float_as_uint(As[kb+tig+4][r  ]);
                a[mt][3] = __float_as_uint(As[kb+tig+4][r+8]);
            }
            #pragma unroll
            for (int nt=0; nt<8; nt++){
                int n = wn*64 + nt*8 + gid;
                b[nt][0] = __float_as_uint(Bs[kb+tig  ][n]);
                b[nt][1] = __float_as_uint(Bs[kb+tig+4][n]);
            }
            #pragma unroll
            for (int mt=0; mt<2; mt++){
                #pragma unroll
                for (int nt=0; nt<8; nt++)
                    asm("mma.sync.aligned.m16n8k8.row.col.f32.tf32.tf32.f32 "
                        "{%0,%1,%2,%3}, {%4,%5,%6,%7}, {%8,%9}, {%0,%1,%2,%3};"
                        : "+f"(c[mt][nt][0]), "+f"(c[mt][nt][1]),
                          "+f"(c[mt][nt][2]), "+f"(c[mt][nt][3])
                        : "r"(a[mt][0]), "r"(a[mt][1]), "r"(a[mt][2]), "r"(a[mt][3]),
                          "r"(b[nt][0]), "r"(b[nt][1]));
            }
        }
        __syncthreads();
    }
    #pragma unroll
    for (int mt=0; mt<2; mt++){
        int r = row0 + wm*32 + mt*16 + gid;
        #pragma unroll
        for (int nt=0; nt<8; nt++){
            int cc = col0 + wn*64 + nt*8 + tig*2;
            Cb[(size_t)r*N + cc]       = __float2bfloat16(c[mt][nt][0]);
            Cb[(size_t)r*N + cc + 1]   = __float2bfloat16(c[mt][nt][1]);
            Cb[(size_t)(r+8)*N + cc]   = __float2bfloat16(c[mt][nt][2]);
            Cb[(size_t)(r+8)*N + cc+1] = __float2bfloat16(c[mt][nt][3]);
        }
    }
}

// tiled SGEMM, packed f32x2 FMA (small GEMMs)
template<int ACT>
__global__ void sgemm_k(const float* __restrict__ A, const float* __restrict__ Bm,
                        const float* __restrict__ bias, float* __restrict__ C,
                        int M, int N, int K)
{
    const int BM=64, BN=128, BK=16, TM=4, TN=8, THREADS=256;
    __shared__ float As[BM][BK+1];
    __shared__ __align__(16) float Bs[BK][BN];
    int tid = threadIdx.x;
    int tx = tid % (BN/TN), ty = tid / (BN/TN);
    int row0 = blockIdx.y*BM, col0 = blockIdx.x*BN;
    unsigned long long acc2[TM][TN/2];
    #pragma unroll
    for (int m=0;m<TM;m++){
        #pragma unroll
        for (int i=0;i<TN/2;i++) acc2[m][i]=0ull;
    }
    for (int k0 = 0; k0 < K; k0 += BK){
        for (int l = tid; l < BM*BK; l += THREADS){
            int r=l/BK, c=l%BK;
            As[r][c] = A[(size_t)(row0+r)*K + k0 + c];
        }
        for (int l = tid; l < BK*BN; l += THREADS){
            int r=l/BN, c=l%BN, gc=col0+c;
            Bs[r][c] = (gc<N) ? Bm[(size_t)(k0+r)*N + gc] : 0.f;
        }
        __syncthreads();
        #pragma unroll
        for (int kk=0; kk<BK; kk++){
            unsigned long long b2[TN/2];
            #pragma unroll
            for (int i=0;i<TN/2;i++)
                b2[i] = *reinterpret_cast<const unsigned long long*>(&Bs[kk][tx*TN+2*i]);
            #pragma unroll
            for (int m=0;m<TM;m++){
                float av = As[ty*TM+m][kk];
                unsigned long long a2;
                asm("mov.b64 %0, {%1, %1};" : "=l"(a2) : "r"(__float_as_uint(av)));
                #pragma unroll
                for (int i=0;i<TN/2;i++)
                    asm("fma.rn.f32x2 %0, %1, %2, %0;" : "+l"(acc2[m][i]) : "l"(a2), "l"(b2[i]));
            }
        }
        __syncthreads();
    }
    #pragma unroll
    for (int m=0;m<TM;m++){
        int gr = row0 + ty*TM + m;
        #pragma unroll
        for (int i=0;i<TN/2;i++){
            unsigned lo,hi;
            asm("mov.b64 {%0, %1}, %2;" : "=r"(lo), "=r"(hi) : "l"(acc2[m][i]));
            int gc0 = col0 + tx*TN + 2*i;
            if (gc0 < N){
                float v = __uint_as_float(lo);
                if (bias) v += bias[gc0];
                if (ACT) v = tanhf(v);
                C[(size_t)gr*N + gc0] = v;
            }
            if (gc0+1 < N){
                float v = __uint_as_float(hi);
                if (bias) v += bias[gc0+1];
                if (ACT) v = tanhf(v);
                C[(size_t)gr*N + gc0+1] = v;
            }
        }
    }
}

// recurrent GEMM: gpart[ks,dir,b,4H] = h_prev[dir,b,:]@Wh[dir] (split-K x4)
__global__ void k_lstm_gemm(const float* __restrict__ Wh_fw, const float* __restrict__ Wh_bw){
    int chunk = blockIdx.x, dir = blockIdx.y, ks = blockIdx.z;
    int tid = threadIdx.x;
    int colid = tid & 127, bg = tid >> 7;
    __shared__ __align__(16) float hsT[128*16];   // [k][b]
    const float* hprev = d_hstate + dir*(B_*H_);
    for (int i = tid; i < 128*16; i += 256){
        int k = i>>4, b = i&15;
        hsT[i] = hprev[b*H_ + ks*128 + k];
    }
    __syncthreads();
    const float* Wh = dir ? Wh_bw : Wh_fw;
    int colg = chunk*128 + colid;
    const float* wp = Wh + (size_t)(ks*128)*G4_ + colg;
    unsigned long long acc2[4] = {0,0,0,0};
    #pragma unroll 4
    for (int k = 0; k < 128; k++){
        float w = wp[(size_t)k*G4_];
        unsigned long long w2;
        asm("mov.b64 %0, {%1, %1};" : "=l"(w2) : "r"(__float_as_uint(w)));
        const unsigned long long* hv = reinterpret_cast<const unsigned long long*>(&hsT[k*16 + bg*8]);
        #pragma unroll
        for (int j=0;j<4;j++)
            asm("fma.rn.f32x2 %0, %1, %2, %0;" : "+l"(acc2[j]) : "l"(hv[j]), "l"(w2));
    }
    float* gp = d_gpart + ((size_t)(ks*2+dir)*B_ + bg*8)*G4_ + colg;
    #pragma unroll
    for (int j=0;j<4;j++){
        unsigned lo,hi;
        asm("mov.b64 {%0, %1}, %2;" : "=r"(lo), "=r"(hi) : "l"(acc2[j]));
        gp[(size_t)(2*j)*G4_]   = __uint_as_float(lo);
        gp[(size_t)(2*j+1)*G4_] = __uint_as_float(hi);
    }
}

__global__ void k_lstm_combine(const int* __restrict__ lengths, int t){
    int b = blockIdx.x, dir = blockIdx.y, h = threadIdx.x;   // 512
    const float* gp = (dir ? d_gpre_bw : d_gpre_fw) + (size_t)(b*T_+t)*G4_;
    float g[4];
    #pragma unroll
    for (int gt=0; gt<4; gt++){
        float a = gp[gt*H_+h];
        #pragma unroll
        for (int ks=0; ks<4; ks++)
            a += d_gpart[((size_t)(ks*2+dir)*B_ + b)*G4_ + gt*H_ + h];
        g[gt] = a;
    }
    int idx = (dir*B_+b)*H_+h;
    float c = d_cstate[idx], hp = d_hstate[idx];
    float cn = sigmf(g[2]+1.f)*c + sigmf(g[0])*tanhf(g[1]);
    float hn = sigmf(g[3])*tanhf(cn);
    int len = lengths[b];
    bool m = (t < len);
    d_cstate[idx] = m ? cn : c;
    d_hstate[idx] = m ? hn : hp;
    float ho = m ? hn : 0.f;
    if (dir == 0) d_hcat[(size_t)(b*T_+t)*(2*H_) + h] = ho;
    else { int p = m ? (len-1-t) : t; d_hcat[(size_t)(b*T_+p)*(2*H_) + H_ + h] = ho; }
}

// single-pass online softmax row reduce over 32000 logits
__global__ void k_rowreduce(){
    int row = blockIdx.x, tid = threadIdx.x;
    const float4* p = reinterpret_cast<const float4*>(d_logits + (size_t)row*VS_);
    float m = -1e30f, s = 0.f;
    for (int v = tid; v < VS_/4; v += 256){
        float4 x = p[v];
        #pragma unroll
        for (int q = 0; q < 4; q++){
            float xv = (q==0)?x.x:(q==1)?x.y:(q==2)?x.z:x.w;
            if (xv > m){ s = s*expf(m - xv) + 1.f; m = xv; }
            else        s += expf(xv - m);
        }
    }
    __shared__ float sm[256], ss[256];
    sm[tid] = m; ss[tid] = s; __syncthreads();
    for (int st = 128; st > 0; st >>= 1){
        if (tid < st){
            float m1 = sm[tid], m2 = sm[tid+st];
            float mm = fmaxf(m1, m2);
            ss[tid] = ss[tid]*expf(m1-mm) + ss[tid+st]*expf(m2-mm);
            sm[tid] = mm;
        }
        __syncthreads();
    }
    if (tid == 0){ d_rowmax[row] = sm[0]; d_rowsum[row] = ss[0]; }
}

__global__ void k_nulllogits(const float* __restrict__ Wv, const float* __restrict__ bv){
    __shared__ float ns[H_];
    int tid = threadIdx.x;
    for (int k=tid; k<H_; k+=256) ns[k] = d_nullstate[k];
    __syncthreads();
    int v = blockIdx.x*256 + tid;
    if (v < VS_){
        float a = bv[v];
        #pragma unroll 4
        for (int k=0;k<H_;k++) a = fmaf(ns[k], Wv[(size_t)k*VS_+v], a);
        d_nulllog[v] = a;
    }
}

__global__ void k_nullreduce(){
    __shared__ float sm[1024];
    int tid = threadIdx.x;
    float m = -1e30f;
    for (int v=tid; v<VS_; v+=1024) m = fmaxf(m, d_nulllog[v]);
    sm[tid]=m; __syncthreads();
    for (int s=512;s>0;s>>=1){ if(tid<s) sm[tid]=fmaxf(sm[tid],sm[tid+s]); __syncthreads(); }
    float mx = sm[0]; __syncthreads();
    float su = 0.f;
    for (int v=tid; v<VS_; v+=1024) su += expf(d_nulllog[v]-mx);
    sm[tid]=su; __syncthreads();
    for (int s=512;s>0;s>>=1){ if(tid<s) sm[tid]+=sm[tid+s]; __syncthreads(); }
    if (tid==0){ d_nullred[0]=mx; d_nullred[1]=sm[0]; }
}

__global__ void k_emission(const int* __restrict__ sources, float* __restrict__ out){
    int bt = blockIdx.x, b = bt>>6, t = bt&63, s = threadIdx.x;   // 64
    int col = sources[b*S_+s];
    float l = d_logits[(size_t)bt*VS_ + col];
    out[(size_t)b*(2*T_*S_) + t*S_ + s] = expf(l - d_rowmax[bt]) / d_rowsum[bt];
    out[(size_t)b*(2*T_*S_) + (T_+t)*S_ + s] = expf(d_nulllog[col]-d_nullred[0]) / d_nullred[1];
}

__global__ void k_jsoftmax(){
    int row = blockIdx.x, tid = threadIdx.x;
    float* p = d_jl + (size_t)row*J_;
    __shared__ float sm[256];
    float m = -1e30f;
    for (int j=tid; j<J_; j+=256) m = fmaxf(m, p[j]);
    sm[tid]=m; __syncthreads();
    for (int s=128;s>0;s>>=1){ if(tid<s) sm[tid]=fmaxf(sm[tid],sm[tid+s]); __syncthreads(); }
    float mx = sm[0]; __syncthreads();
    float su = 0.f;
    for (int j=tid; j<J_; j+=256) su += expf(p[j]-mx);
    sm[tid]=su; __syncthreads();
    for (int s=128;s>0;s>>=1){ if(tid<s) sm[tid]+=sm[tid+s]; __syncthreads(); }
    float inv = 1.f/sm[0]; __syncthreads();
    for (int j=tid; j<J_; j+=256) p[j] = expf(p[j]-mx)*inv;
}

__global__ void k_p0(const float* __restrict__ Wp0, const float* __restrict__ bp0){
    int gw = (blockIdx.x*blockDim.x + threadIdx.x) >> 5;
    int lane = threadIdx.x & 31;
    if (gw >= BT_) return;
    float a = 0.f;
    for (int k=lane; k<H_; k+=32) a = fmaf(d_tt[(size_t)gw*H_+k], Wp0[k], a);
    #pragma unroll
    for (int o=16;o>0;o>>=1) a += __shfl_xor_sync(0xffffffffu, a, o);
    if (lane==0) d_p0v[gw] = sigmf(a + bp0[0]);
}

__global__ void k_transition(float* __restrict__ out){
    int b = blockIdx.y;
    int idx = blockIdx.x*256 + threadIdx.x;     // over T*2T = 8192
    if (idx >= T_*2*T_) return;
    int i = idx / (2*T_), c = idx % (2*T_);
    float tv, lv;
    if (c < T_){
        float jw = d_jl[(size_t)(b*T_+i)*J_ + (MM_ + c - i)];
        tv = jw; lv = logf(jw);
    } else {
        int j = c - T_;
        float p = d_p0v[b*T_+i];
        tv = (i==j) ? p : 0.f;
        lv = (i==j) ? logf(p) : 0.f;
    }
    float* tr  = out + (size_t)B_*2*T_*S_ + (size_t)b*(2*T_*2*T_);
    float* trl = tr + (size_t)B_*2*T_*2*T_;
    tr [i*2*T_ + c] = tv;  tr [(T_+i)*2*T_ + c] = tv;
    trl[i*2*T_ + c] = lv;  trl[(T_+i)*2*T_ + c] = lv;
}

extern "C" void kernel_launch(void* const* d_in, const int* in_sizes, int n_in,
                              void* d_out, int out_size) {
    const int*   sources = (const int*)  d_in[0];
    const int*   targets = (const int*)  d_in[1];
    const int*   tnull   = (const int*)  d_in[2];
    const int*   lengths = (const int*)  d_in[3];
    const float* emb     = (const float*)d_in[4];
    const float* nnW     = (const float*)d_in[5];
    const float* nnb     = (const float*)d_in[6];
    const float* Wx_fw   = (const float*)d_in[7];
    const float* Wh_fw   = (const float*)d_in[8];
    const float* b_fw    = (const float*)d_in[9];
    const float* Wx_bw   = (const float*)d_in[10];
    const float* Wh_bw   = (const float*)d_in[11];
    const float* b_bw    = (const float*)d_in[12];
    const float* Wproj_e = (const float*)d_in[13];
    const float* Wv      = (const float*)d_in[14];
    const float* bv      = (const float*)d_in[15];
    const float* Wproj_t = (const float*)d_in[16];
    const float* Wj      = (const float*)d_in[17];
    const float* bj      = (const float*)d_in[18];
    const float* Wp0     = (const float*)d_in[19];
    const float* bp0     = (const float*)d_in[20];
    float* out = (float*)d_out;

    float *gfw, *gbw, *xp, *xrp, *hc, *lg, *tmp, *ttp, *jl;
    __nv_bfloat16 *tsb, *wvT;
    cudaGetSymbolAddress((void**)&gfw, d_gpre_fw);
    cudaGetSymbolAddress((void**)&gbw, d_gpre_bw);
    cudaGetSymbolAddress((void**)&xp,  d_x);
    cudaGetSymbolAddress((void**)&xrp, d_xrev);
    cudaGetSymbolAddress((void**)&hc,  d_hcat);
    cudaGetSymbolAddress((void**)&lg,  d_logits);
    cudaGetSymbolAddress((void**)&tmp, d_tmpt);
    cudaGetSymbolAddress((void**)&ttp, d_tt);
    cudaGetSymbolAddress((void**)&jl,  d_jl);
    cudaGetSymbolAddress((void**)&tsb, d_tsb);
    cudaGetSymbolAddress((void**)&wvT, d_wvT);

    k_init<<<64,256>>>();
    k_embed<<<BT_,256>>>(targets, lengths, emb);
    k_nullstate<<<1,512>>>(tnull, emb, nnW, nnb);
    k_cvt_wvT<<<dim3(1000,16),dim3(32,8)>>>(Wv);

    // input projections for all timesteps (fp32 — feeds the recurrence)
    sgemm_k<0><<<dim3(16,16),256>>>(xp,  Wx_fw, b_fw, gfw, BT_, G4_, E_);
    sgemm_k<0><<<dim3(16,16),256>>>(xrp, Wx_bw, b_bw, gbw, BT_, G4_, E_);

    for (int t = 0; t < T_; t++){
        k_lstm_gemm<<<dim3(16,2,4),256>>>(Wh_fw, Wh_bw);
        k_lstm_combine<<<dim3(B_,2),512>>>(lengths, t);
    }

    // emission path: proj_e (tf32 -> bf16 out), logits (bf16 ldmatrix + cp.async)
    tf32gemm_bf16o_k<<<dim3(8,4),256>>>(hc, Wproj_e, tsb, BT_, H_, 2*H_);
    bf16gemm_k<<<dim3(8,250),256>>>(tsb, wvT, bv, lg, BT_, VS_, H_);
    k_rowreduce<<<BT_,256>>>();
    k_nulllogits<<<125,256>>>(Wv, bv);
    k_nullreduce<<<1,1024>>>();
    k_emission<<<BT_,64>>>(sources, out);

    // transition path (fp32, small)
    sgemm_k<0><<<dim3(2,16),256>>>(hc, Wproj_t, nullptr, tmp, BT_, E_, 2*H_);
    sgemm_k<1><<<dim3(4,16),256>>>(tmp, nnW, nnb, ttp, BT_, H_, E_);
    sgemm_k<0><<<dim3(2,16),256>>>(ttp, Wj, bj, jl, BT_, J_, H_);
    k_jsoftmax<<<BT_,256>>>();
    k_p0<<<128,256>>>(Wp0, bp0);
    k_transition<<<dim3(32,16),256>>>(out);
}